// round 5
// baseline (speedup 1.0000x reference)
#include <cuda_runtime.h>
#include <cuda_bf16.h>
#include <math.h>
#include <cstdint>

// ---------------------------------------------------------------------------
// TreeGetter: 11-level conv halving tree as implicit GEMM on mma.sync (bf16,
// hi/lo 3-product split for ~fp32 accuracy). M flattened = batch*P.
// 256 threads / 8 warps, warp tile 64x64, block 128x256x32, 3-stage cp.async
// pipeline, one __syncthreads per K-chunk.
// ---------------------------------------------------------------------------

#define CDIM 768
#define CK   2304
#define NLEV 11
#define BZ   16
#define BM   128
#define BN   256
#define BKC  32
#define NCH  (CK / BKC)      // 72
#define STAGES 3

#define ASTRIDE 40           // bf16 elems per A row (32 + 8 pad) = 80B
#define BSTRIDE 264          // bf16 elems per B row (256 + 8 pad) = 528B
#define A_BYTES (BM * ASTRIDE * 2)               // 10240
#define B_BYTES (BKC * BSTRIDE * 2)              // 16896
#define STAGE_BYTES (2 * A_BYTES + 2 * B_BYTES)  // 54272
#define SMEM_BYTES (STAGES * STAGE_BYTES)        // 162816

// ---------------- scratch (device globals; allocation-free rule) ------------
#define MAXE ((long)BZ * 2048 * CDIM)
__device__ __nv_bfloat16 g_xhi[MAXE], g_xlo[MAXE];   // conv1 input splits
__device__ __nv_bfloat16 g_hhi[MAXE], g_hlo[MAXE];   // conv2 input splits
// weights transposed to [kg][o], kg = d*768 + i
__device__ __nv_bfloat16 g_w1hi[CK * CDIM], g_w1lo[CK * CDIM];
__device__ __nv_bfloat16 g_w2hi[CK * CDIM], g_w2lo[CK * CDIM];

__device__ __forceinline__ void split_bf16(float v, __nv_bfloat16& hi,
                                           __nv_bfloat16& lo) {
    hi = __float2bfloat16(v);
    lo = __float2bfloat16(v - __bfloat162float(hi));
}

__device__ __forceinline__ uint32_t smem_u32(const void* p) {
    uint32_t a;
    asm("{ .reg .u64 t; cvta.to.shared.u64 t, %1; cvt.u32.u64 %0, t; }"
        : "=r"(a) : "l"(p));
    return a;
}
__device__ __forceinline__ void cp_async16(uint32_t dst, const void* src,
                                           bool pred) {
    int sz = pred ? 16 : 0;
    asm volatile("cp.async.cg.shared.global [%0], [%1], 16, %2;"
                 :: "r"(dst), "l"(src), "r"(sz));
}
__device__ __forceinline__ void cp_commit() {
    asm volatile("cp.async.commit_group;");
}
__device__ __forceinline__ void ldsm_x4(uint32_t* r, uint32_t a) {
    asm volatile("ldmatrix.sync.aligned.m8n8.x4.shared.b16 {%0,%1,%2,%3}, [%4];"
                 : "=r"(r[0]), "=r"(r[1]), "=r"(r[2]), "=r"(r[3]) : "r"(a));
}
__device__ __forceinline__ void ldsm_x4_t(uint32_t* r, uint32_t a) {
    asm volatile("ldmatrix.sync.aligned.m8n8.x4.trans.shared.b16 {%0,%1,%2,%3}, [%4];"
                 : "=r"(r[0]), "=r"(r[1]), "=r"(r[2]), "=r"(r[3]) : "r"(a));
}
__device__ __forceinline__ void mma16816(float* d, const uint32_t* a,
                                         const uint32_t* b) {
    asm volatile(
        "mma.sync.aligned.m16n8k16.row.col.f32.bf16.bf16.f32 "
        "{%0,%1,%2,%3}, {%4,%5,%6,%7}, {%8,%9}, {%0,%1,%2,%3};"
        : "+f"(d[0]), "+f"(d[1]), "+f"(d[2]), "+f"(d[3])
        : "r"(a[0]), "r"(a[1]), "r"(a[2]), "r"(a[3]), "r"(b[0]), "r"(b[1]));
}

// ---------------------------------------------------------------------------
__global__ void prep_weights(const float* __restrict__ w1,
                             const float* __restrict__ w2) {
    int total = CK * CDIM;
    for (int j = blockIdx.x * blockDim.x + threadIdx.x; j < total;
         j += gridDim.x * blockDim.x) {
        int o  = j % CDIM;
        int kg = j / CDIM;
        int d  = kg / CDIM;
        int i  = kg - d * CDIM;
        long src = (long)o * CK + i * 3 + d;   // w[o][i][d]
        split_bf16(w1[src], g_w1hi[j], g_w1lo[j]);
        split_bf16(w2[src], g_w2hi[j], g_w2lo[j]);
    }
}

__global__ void prep_input(const float* __restrict__ seq,
                           const int* __restrict__ lengths) {
    long total = MAXE;
    for (long j = blockIdx.x * (long)blockDim.x + threadIdx.x; j < total;
         j += gridDim.x * (long)blockDim.x) {
        long bp = j / CDIM;
        int p = (int)(bp % 2048);
        int b = (int)(bp / 2048);
        float v = (p < lengths[b]) ? seq[j] : 0.f;
        split_bf16(v, g_xhi[j], g_xlo[j]);
    }
}

__global__ void mask_kernel(float* __restrict__ out,
                            const int* __restrict__ lengths) {
    int idx    = blockIdx.x * blockDim.x + threadIdx.x;
    int stride = gridDim.x * blockDim.x;
    long off = 0;
    int P = 2048;
    for (int lvl = 0; lvl < NLEV; lvl++) {
        int Pout = (P - 1) / 2 + 1;
        long maskOff = off + (long)BZ * Pout * CDIM;
        int n = BZ * Pout;
        for (int i = idx; i < n; i += stride) {
            int b = i / Pout, p = i % Pout;
            int L = lengths[b];
            for (int t = 0; t <= lvl; t++) L = (L - 1) / 2 + 1;
            out[maskOff + i] = (p < L) ? 1.f : 0.f;
        }
        off = maskOff + n;
        P = Pout;
    }
}

// ---------------------------------------------------------------------------
// Implicit-GEMM conv on mma.sync. 256 threads = 8 warps (2M x 4N), warp tile
// 64x64, block 128x256x32, 3-stage pipeline, 1 sync per chunk.
template <int STRIDE, bool DO_GELU>
__global__ void __launch_bounds__(256, 1)
conv_mma(const float* __restrict__ bias, float* __restrict__ outY,
         int Pin, int Pout, const int* __restrict__ lengths, int level) {
    extern __shared__ char smem[];
    const uint32_t sbase = smem_u32(smem);
    const int tid   = threadIdx.x;
    const int lane  = tid & 31;
    const int wid   = tid >> 5;
    const int warpM = (wid & 1) * 64;
    const int warpN = (wid >> 1) * 64;
    const int p0    = blockIdx.x * BM;
    const int n0    = blockIdx.y * BN;
    const int Mtot  = BZ * Pout;

    const __nv_bfloat16* Xhi = DO_GELU ? g_xhi : g_hhi;
    const __nv_bfloat16* Xlo = DO_GELU ? g_xlo : g_hlo;
    const __nv_bfloat16* Whi = DO_GELU ? g_w1hi : g_w2hi;
    const __nv_bfloat16* Wlo = DO_GELU ? g_w1lo : g_w2lo;

    // ---- per-thread load geometry ----
    // A: 512 16B-chunks per buffer: id = tid + i*256; row=id>>2, kc=id&3
    int aPosB[2]; long aRowBase[2]; bool aOk[2];
    const int akc = tid & 3;
#pragma unroll
    for (int i = 0; i < 2; i++) {
        int r = (tid + i * 256) >> 2;
        int grow = p0 + r;
        bool ok = grow < Mtot;
        int b = ok ? grow / Pout : 0;
        int p = grow - b * Pout;
        aOk[i] = ok;
        aPosB[i] = p * STRIDE - 1;
        aRowBase[i] = (long)b * Pin;
    }
    // B: 1024 chunks per buffer: id = tid + i*256; krow=id>>5, nc=id&31
    const int bnc = tid & 31;

    float acc[4][8][4];
#pragma unroll
    for (int a = 0; a < 4; a++)
#pragma unroll
        for (int b = 0; b < 8; b++)
#pragma unroll
            for (int c = 0; c < 4; c++) acc[a][b][c] = 0.f;

    // ldmatrix per-lane base offsets (bytes)
    const uint32_t aoff =
        ((warpM + (lane & 15)) * ASTRIDE + ((lane >> 4) << 3)) * 2;
    const uint32_t boff =
        ((lane & 15) * BSTRIDE + warpN + ((lane >> 4) << 3)) * 2;

    // ---- stage loader ----
    auto load_stage = [&](int slot, int it) {
        const uint32_t sa = sbase + slot * STAGE_BYTES;
        const int kk = it * BKC;
        const int d  = (kk >= 1536) ? 2 : (kk >= 768 ? 1 : 0);
        const int c0 = kk - d * CDIM;
#pragma unroll
        for (int i = 0; i < 2; i++) {
            int row = (tid + i * 256) >> 2;
            int pos = aPosB[i] + d;
            bool v = aOk[i] && pos >= 0 && pos < Pin;
            long g = v ? ((aRowBase[i] + pos) * CDIM + c0 + akc * 8) : 0;
            uint32_t dst = sa + (row * ASTRIDE + akc * 8) * 2;
            cp_async16(dst, Xhi + g, v);
            cp_async16(dst + A_BYTES, Xlo + g, v);
        }
#pragma unroll
        for (int i = 0; i < 4; i++) {
            int krow = (tid + i * 256) >> 5;
            long g = (long)(kk + krow) * CDIM + n0 + bnc * 8;
            uint32_t dst = sa + 2 * A_BYTES + (krow * BSTRIDE + bnc * 8) * 2;
            cp_async16(dst, Whi + g, true);
            cp_async16(dst + B_BYTES, Wlo + g, true);
        }
        cp_commit();
    };

    // ---- pipeline: wait -> sync -> prefetch(it+2) -> compute(it) ----
    load_stage(0, 0);
    load_stage(1, 1);

#pragma unroll 1
    for (int it = 0; it < NCH; it++) {
        asm volatile("cp.async.wait_group %0;" :: "n"(1));
        __syncthreads();
        int pre = it + 2;
        if (pre < NCH) load_stage(pre % STAGES, pre);
        else cp_commit();   // keep group count uniform

        const uint32_t sa = sbase + (it % STAGES) * STAGE_BYTES;
        const uint32_t aaddr = sa + aoff;
        const uint32_t baddr = sa + 2 * A_BYTES + boff;
#pragma unroll
        for (int ks2 = 0; ks2 < 2; ks2++) {
            const int ks = ks2 * 16;
            uint32_t ah[4][4], al[4][4];
#pragma unroll
            for (int mt = 0; mt < 4; mt++) {
                ldsm_x4(ah[mt], aaddr + (mt * 16 * ASTRIDE + ks) * 2);
                ldsm_x4(al[mt], aaddr + A_BYTES + (mt * 16 * ASTRIDE + ks) * 2);
            }
#pragma unroll
            for (int np = 0; np < 4; np++) {
                uint32_t bh[4], bl[4];
                ldsm_x4_t(bh, baddr + (ks * BSTRIDE + np * 16) * 2);
                ldsm_x4_t(bl, baddr + B_BYTES + (ks * BSTRIDE + np * 16) * 2);
#pragma unroll
                for (int mt = 0; mt < 4; mt++)
#pragma unroll
                    for (int sub = 0; sub < 2; sub++) {
                        float* d = acc[mt][np * 2 + sub];
                        mma16816(d, ah[mt], &bh[sub * 2]);
                        mma16816(d, ah[mt], &bl[sub * 2]);
                        mma16816(d, al[mt], &bh[sub * 2]);
                    }
            }
        }
    }

    // ---- epilogue ----
    const int mrow0 = p0 + warpM + (lane >> 2);
    const int colb  = n0 + warpN + 2 * (lane & 3);
#pragma unroll
    for (int mt = 0; mt < 4; mt++) {
#pragma unroll
        for (int half = 0; half < 2; half++) {
            int row = mrow0 + mt * 16 + half * 8;
            if (row >= Mtot) continue;
            int b = row / Pout;
            int p = row - b * Pout;
            int L = lengths[b];
            for (int t = 0; t < level; t++) L = (L - 1) / 2 + 1;
            int lenOut = DO_GELU ? L : ((L - 1) / 2 + 1);
            bool valid = p < lenOut;
            long base = (long)row * CDIM;
#pragma unroll
            for (int nt = 0; nt < 8; nt++) {
                int col = colb + nt * 8;
                float z0 = 0.f, z1 = 0.f;
                if (valid) {
                    z0 = acc[mt][nt][half * 2 + 0] + __ldg(&bias[col]);
                    z1 = acc[mt][nt][half * 2 + 1] + __ldg(&bias[col + 1]);
                    if (DO_GELU) {
                        z0 = 0.5f * z0 * (1.f + erff(z0 * 0.70710678118654752f));
                        z1 = 0.5f * z1 * (1.f + erff(z1 * 0.70710678118654752f));
                    }
                }
                __nv_bfloat162 h2, l2;
                split_bf16(z0, h2.x, l2.x);
                split_bf16(z1, h2.y, l2.y);
                if (DO_GELU) {
                    *(__nv_bfloat162*)(g_hhi + base + col) = h2;
                    *(__nv_bfloat162*)(g_hlo + base + col) = l2;
                } else {
                    float2 o2 = make_float2(z0, z1);
                    *(float2*)(outY + base + col) = o2;
                    *(__nv_bfloat162*)(g_xhi + base + col) = h2;
                    *(__nv_bfloat162*)(g_xlo + base + col) = l2;
                }
            }
        }
    }
}

// ---------------------------------------------------------------------------
extern "C" void kernel_launch(void* const* d_in, const int* in_sizes, int n_in,
                              void* d_out, int out_size) {
    const float* seq     = (const float*)d_in[0];
    const int*   lengths = (const int*)  d_in[1];
    const float* w1      = (const float*)d_in[2];
    const float* b1      = (const float*)d_in[3];
    const float* w2      = (const float*)d_in[4];
    const float* b2      = (const float*)d_in[5];
    float* out = (float*)d_out;

    cudaFuncSetAttribute(conv_mma<1, true>,
                         cudaFuncAttributeMaxDynamicSharedMemorySize, SMEM_BYTES);
    cudaFuncSetAttribute(conv_mma<2, false>,
                         cudaFuncAttributeMaxDynamicSharedMemorySize, SMEM_BYTES);

    prep_weights<<<256, 256>>>(w1, w2);
    prep_input<<<512, 256>>>(seq, lengths);
    mask_kernel<<<64, 256>>>(out, lengths);

    int P = 2048;
    long off = 0;
    for (int lvl = 0; lvl < NLEV; lvl++) {
        int Pout = (P - 1) / 2 + 1;
        dim3 g1((BZ * P + BM - 1) / BM, CDIM / BN);
        conv_mma<1, true><<<g1, 256, SMEM_BYTES>>>(b1, nullptr, P, P,
                                                   lengths, lvl);
        dim3 g2((BZ * Pout + BM - 1) / BM, CDIM / BN);
        conv_mma<2, false><<<g2, 256, SMEM_BYTES>>>(b2, out + off, P, Pout,
                                                    lengths, lvl);
        off += (long)BZ * Pout * CDIM + (long)BZ * Pout;
        P = Pout;
    }
}

// round 6
// speedup vs baseline: 1.1706x; 1.1706x over previous
#include <cuda_runtime.h>
#include <cuda_bf16.h>
#include <math.h>
#include <cstdint>

// ---------------------------------------------------------------------------
// TreeGetter: 11-level conv halving tree as implicit GEMM on mma.sync (bf16,
// hi/lo 3-product split for ~fp32 accuracy). M flattened = batch*P.
// R3 config (128x128x32 block, 8 warps, 64x32 warp tile, 3-stage cp.async)
// with product-major MMA ordering (RAW distance 16) and non-volatile mma.
// ---------------------------------------------------------------------------

#define CDIM 768
#define CK   2304
#define NLEV 11
#define BZ   16
#define BM   128
#define BN   128
#define BKC  32
#define NCH  (CK / BKC)      // 72
#define STAGES 3

#define ASTRIDE 40           // bf16 elems per A row (32 + 8 pad) = 80B
#define BSTRIDE 136          // bf16 elems per B row (128 + 8 pad) = 272B
#define A_BYTES (BM * ASTRIDE * 2)               // 10240
#define B_BYTES (BKC * BSTRIDE * 2)              // 8704
#define STAGE_BYTES (2 * A_BYTES + 2 * B_BYTES)  // 37888
#define SMEM_BYTES (STAGES * STAGE_BYTES)        // 113664

// ---------------- scratch (device globals; allocation-free rule) ------------
#define MAXE ((long)BZ * 2048 * CDIM)
__device__ __nv_bfloat16 g_xhi[MAXE], g_xlo[MAXE];   // conv1 input splits
__device__ __nv_bfloat16 g_hhi[MAXE], g_hlo[MAXE];   // conv2 input splits
// weights transposed to [kg][o], kg = d*768 + i
__device__ __nv_bfloat16 g_w1hi[CK * CDIM], g_w1lo[CK * CDIM];
__device__ __nv_bfloat16 g_w2hi[CK * CDIM], g_w2lo[CK * CDIM];

__device__ __forceinline__ void split_bf16(float v, __nv_bfloat16& hi,
                                           __nv_bfloat16& lo) {
    hi = __float2bfloat16(v);
    lo = __float2bfloat16(v - __bfloat162float(hi));
}

__device__ __forceinline__ uint32_t smem_u32(const void* p) {
    uint32_t a;
    asm("{ .reg .u64 t; cvta.to.shared.u64 t, %1; cvt.u32.u64 %0, t; }"
        : "=r"(a) : "l"(p));
    return a;
}
__device__ __forceinline__ void cp_async16(uint32_t dst, const void* src,
                                           bool pred) {
    int sz = pred ? 16 : 0;
    asm volatile("cp.async.cg.shared.global [%0], [%1], 16, %2;"
                 :: "r"(dst), "l"(src), "r"(sz));
}
__device__ __forceinline__ void cp_commit() {
    asm volatile("cp.async.commit_group;");
}
__device__ __forceinline__ void ldsm_x4(uint32_t* r, uint32_t a) {
    asm volatile("ldmatrix.sync.aligned.m8n8.x4.shared.b16 {%0,%1,%2,%3}, [%4];"
                 : "=r"(r[0]), "=r"(r[1]), "=r"(r[2]), "=r"(r[3]) : "r"(a));
}
__device__ __forceinline__ void ldsm_x4_t(uint32_t* r, uint32_t a) {
    asm volatile("ldmatrix.sync.aligned.m8n8.x4.trans.shared.b16 {%0,%1,%2,%3}, [%4];"
                 : "=r"(r[0]), "=r"(r[1]), "=r"(r[2]), "=r"(r[3]) : "r"(a));
}
// NOTE: non-volatile — no side effects, lets the compiler interleave
// independent MMAs across accumulator tiles.
__device__ __forceinline__ void mma16816(float* d, const uint32_t* a,
                                         const uint32_t* b) {
    asm("mma.sync.aligned.m16n8k16.row.col.f32.bf16.bf16.f32 "
        "{%0,%1,%2,%3}, {%4,%5,%6,%7}, {%8,%9}, {%0,%1,%2,%3};"
        : "+f"(d[0]), "+f"(d[1]), "+f"(d[2]), "+f"(d[3])
        : "r"(a[0]), "r"(a[1]), "r"(a[2]), "r"(a[3]), "r"(b[0]), "r"(b[1]));
}

// ---------------------------------------------------------------------------
__global__ void prep_weights(const float* __restrict__ w1,
                             const float* __restrict__ w2) {
    int total = CK * CDIM;
    for (int j = blockIdx.x * blockDim.x + threadIdx.x; j < total;
         j += gridDim.x * blockDim.x) {
        int o  = j % CDIM;
        int kg = j / CDIM;
        int d  = kg / CDIM;
        int i  = kg - d * CDIM;
        long src = (long)o * CK + i * 3 + d;   // w[o][i][d]
        split_bf16(w1[src], g_w1hi[j], g_w1lo[j]);
        split_bf16(w2[src], g_w2hi[j], g_w2lo[j]);
    }
}

__global__ void prep_input(const float* __restrict__ seq,
                           const int* __restrict__ lengths) {
    long total = MAXE;
    for (long j = blockIdx.x * (long)blockDim.x + threadIdx.x; j < total;
         j += gridDim.x * (long)blockDim.x) {
        long bp = j / CDIM;
        int p = (int)(bp % 2048);
        int b = (int)(bp / 2048);
        float v = (p < lengths[b]) ? seq[j] : 0.f;
        split_bf16(v, g_xhi[j], g_xlo[j]);
    }
}

__global__ void mask_kernel(float* __restrict__ out,
                            const int* __restrict__ lengths) {
    int idx    = blockIdx.x * blockDim.x + threadIdx.x;
    int stride = gridDim.x * blockDim.x;
    long off = 0;
    int P = 2048;
    for (int lvl = 0; lvl < NLEV; lvl++) {
        int Pout = (P - 1) / 2 + 1;
        long maskOff = off + (long)BZ * Pout * CDIM;
        int n = BZ * Pout;
        for (int i = idx; i < n; i += stride) {
            int b = i / Pout, p = i % Pout;
            int L = lengths[b];
            for (int t = 0; t <= lvl; t++) L = (L - 1) / 2 + 1;
            out[maskOff + i] = (p < L) ? 1.f : 0.f;
        }
        off = maskOff + n;
        P = Pout;
    }
}

// ---------------------------------------------------------------------------
// Implicit-GEMM conv on mma.sync.  M rows flattened over (b, p).
// 256 threads = 8 warps (2 M x 4 N), warp tile 64x32, block 128x128x32.
template <int STRIDE, bool DO_GELU>
__global__ void __launch_bounds__(256, 1)
conv_mma(const float* __restrict__ bias, float* __restrict__ outY,
         int Pin, int Pout, const int* __restrict__ lengths, int level) {
    extern __shared__ char smem[];
    const uint32_t sbase = smem_u32(smem);
    const int tid   = threadIdx.x;
    const int lane  = tid & 31;
    const int wid   = tid >> 5;
    const int warpM = (wid & 1) * 64;
    const int warpN = (wid >> 1) * 32;
    const int p0    = blockIdx.x * BM;
    const int n0    = blockIdx.y * BN;
    const int Mtot  = BZ * Pout;

    const __nv_bfloat16* Xhi = DO_GELU ? g_xhi : g_hhi;
    const __nv_bfloat16* Xlo = DO_GELU ? g_xlo : g_hlo;
    const __nv_bfloat16* Whi = DO_GELU ? g_w1hi : g_w2hi;
    const __nv_bfloat16* Wlo = DO_GELU ? g_w1lo : g_w2lo;

    // ---- per-thread load geometry (fixed across stages) ----
    int aPosB[2]; long aRowBase[2]; bool aOk[2];
    const int akc = tid & 3;
#pragma unroll
    for (int i = 0; i < 2; i++) {
        int r = (tid + i * 256) >> 2;
        int grow = p0 + r;
        bool ok = grow < Mtot;
        int b = ok ? grow / Pout : 0;
        int p = grow - b * Pout;
        aOk[i] = ok;
        aPosB[i] = p * STRIDE - 1;
        aRowBase[i] = (long)b * Pin;
    }
    const int bkrow0 = tid >> 4;           // +16 for second
    const int bnc = tid & 15;

    float acc[4][4][4];
#pragma unroll
    for (int a = 0; a < 4; a++)
#pragma unroll
        for (int b = 0; b < 4; b++)
#pragma unroll
            for (int c = 0; c < 4; c++) acc[a][b][c] = 0.f;

    // ldmatrix per-lane offsets (bytes)
    const uint32_t aoff =
        ((warpM + (lane & 15)) * ASTRIDE + ((lane >> 4) << 3)) * 2;
    const uint32_t boff =
        ((lane & 15) * BSTRIDE + warpN + ((lane >> 4) << 3)) * 2;

    // ---- stage loader ----
    auto load_stage = [&](int slot, int it) {
        const uint32_t sa = sbase + slot * STAGE_BYTES;
        const int kk = it * BKC;
        const int d  = (kk >= 1536) ? 2 : (kk >= 768 ? 1 : 0);
        const int c0 = kk - d * CDIM;
#pragma unroll
        for (int i = 0; i < 2; i++) {
            int id  = tid + i * 256;
            int row = id >> 2;
            int pos = aPosB[i] + d;
            bool v = aOk[i] && pos >= 0 && pos < Pin;
            long g = v ? ((aRowBase[i] + pos) * CDIM + c0 + akc * 8) : 0;
            uint32_t dst = sa + (row * ASTRIDE + akc * 8) * 2;
            cp_async16(dst, Xhi + g, v);
            cp_async16(dst + A_BYTES, Xlo + g, v);
        }
#pragma unroll
        for (int i = 0; i < 2; i++) {
            int krow = bkrow0 + i * 16;
            long g = (long)(kk + krow) * CDIM + n0 + bnc * 8;
            uint32_t dst = sa + 2 * A_BYTES + (krow * BSTRIDE + bnc * 8) * 2;
            cp_async16(dst, Whi + g, true);
            cp_async16(dst + B_BYTES, Wlo + g, true);
        }
        cp_commit();
    };

    // ---- pipeline ----
#pragma unroll
    for (int s = 0; s < STAGES - 1; s++) load_stage(s, s);

#pragma unroll 1
    for (int it = 0; it < NCH; it++) {
        int pre = it + STAGES - 1;
        if (pre < NCH) load_stage(pre % STAGES, pre);
        else cp_commit();
        asm volatile("cp.async.wait_group %0;" :: "n"(STAGES - 1));
        __syncthreads();

        const uint32_t sa = sbase + (it % STAGES) * STAGE_BYTES;
        const uint32_t aaddr = sa + aoff;
        const uint32_t baddr = sa + 2 * A_BYTES + boff;
#pragma unroll
        for (int ks2 = 0; ks2 < 2; ks2++) {
            const int ks = ks2 * 16;
            uint32_t ah[4][4], al[4][4], bh[2][4], bl[2][4];
#pragma unroll
            for (int mt = 0; mt < 4; mt++) {
                ldsm_x4(ah[mt], aaddr + (mt * 16 * ASTRIDE + ks) * 2);
                ldsm_x4(al[mt], aaddr + A_BYTES + (mt * 16 * ASTRIDE + ks) * 2);
            }
#pragma unroll
            for (int np = 0; np < 2; np++) {
                ldsm_x4_t(bh[np], baddr + (ks * BSTRIDE + np * 16) * 2);
                ldsm_x4_t(bl[np], baddr + B_BYTES + (ks * BSTRIDE + np * 16) * 2);
            }
            // product-major ordering: RAW distance on each acc tile = 16 MMAs
#pragma unroll
            for (int mt = 0; mt < 4; mt++)
#pragma unroll
                for (int nt = 0; nt < 4; nt++)
                    mma16816(acc[mt][nt], ah[mt], &bh[nt >> 1][(nt & 1) * 2]);
#pragma unroll
            for (int mt = 0; mt < 4; mt++)
#pragma unroll
                for (int nt = 0; nt < 4; nt++)
                    mma16816(acc[mt][nt], ah[mt], &bl[nt >> 1][(nt & 1) * 2]);
#pragma unroll
            for (int mt = 0; mt < 4; mt++)
#pragma unroll
                for (int nt = 0; nt < 4; nt++)
                    mma16816(acc[mt][nt], al[mt], &bh[nt >> 1][(nt & 1) * 2]);
        }
        __syncthreads();
    }

    // ---- epilogue ----
    const int mrow0 = p0 + warpM + (lane >> 2);
    const int colb  = n0 + warpN + 2 * (lane & 3);
#pragma unroll
    for (int mt = 0; mt < 4; mt++) {
#pragma unroll
        for (int half = 0; half < 2; half++) {
            int row = mrow0 + mt * 16 + half * 8;
            if (row >= Mtot) continue;
            int b = row / Pout;
            int p = row - b * Pout;
            int L = lengths[b];
            for (int t = 0; t < level; t++) L = (L - 1) / 2 + 1;
            int lenOut = DO_GELU ? L : ((L - 1) / 2 + 1);
            bool valid = p < lenOut;
            long base = (long)row * CDIM;
#pragma unroll
            for (int nt = 0; nt < 4; nt++) {
                int col = colb + nt * 8;
                float z0 = 0.f, z1 = 0.f;
                if (valid) {
                    z0 = acc[mt][nt][half * 2 + 0] + __ldg(&bias[col]);
                    z1 = acc[mt][nt][half * 2 + 1] + __ldg(&bias[col + 1]);
                    if (DO_GELU) {
                        z0 = 0.5f * z0 * (1.f + erff(z0 * 0.70710678118654752f));
                        z1 = 0.5f * z1 * (1.f + erff(z1 * 0.70710678118654752f));
                    }
                }
                __nv_bfloat162 h2, l2;
                split_bf16(z0, h2.x, l2.x);
                split_bf16(z1, h2.y, l2.y);
                if (DO_GELU) {
                    *(__nv_bfloat162*)(g_hhi + base + col) = h2;
                    *(__nv_bfloat162*)(g_hlo + base + col) = l2;
                } else {
                    float2 o2 = make_float2(z0, z1);
                    *(float2*)(outY + base + col) = o2;
                    *(__nv_bfloat162*)(g_xhi + base + col) = h2;
                    *(__nv_bfloat162*)(g_xlo + base + col) = l2;
                }
            }
        }
    }
}

// ---------------------------------------------------------------------------
extern "C" void kernel_launch(void* const* d_in, const int* in_sizes, int n_in,
                              void* d_out, int out_size) {
    const float* seq     = (const float*)d_in[0];
    const int*   lengths = (const int*)  d_in[1];
    const float* w1      = (const float*)d_in[2];
    const float* b1      = (const float*)d_in[3];
    const float* w2      = (const float*)d_in[4];
    const float* b2      = (const float*)d_in[5];
    float* out = (float*)d_out;

    cudaFuncSetAttribute(conv_mma<1, true>,
                         cudaFuncAttributeMaxDynamicSharedMemorySize, SMEM_BYTES);
    cudaFuncSetAttribute(conv_mma<2, false>,
                         cudaFuncAttributeMaxDynamicSharedMemorySize, SMEM_BYTES);

    prep_weights<<<256, 256>>>(w1, w2);
    prep_input<<<512, 256>>>(seq, lengths);
    mask_kernel<<<64, 256>>>(out, lengths);

    int P = 2048;
    long off = 0;
    for (int lvl = 0; lvl < NLEV; lvl++) {
        int Pout = (P - 1) / 2 + 1;
        dim3 g1((BZ * P + BM - 1) / BM, CDIM / BN);
        conv_mma<1, true><<<g1, 256, SMEM_BYTES>>>(b1, nullptr, P, P,
                                                   lengths, lvl);
        dim3 g2((BZ * Pout + BM - 1) / BM, CDIM / BN);
        conv_mma<2, false><<<g2, 256, SMEM_BYTES>>>(b2, out + off, P, Pout,
                                                    lengths, lvl);
        off += (long)BZ * Pout * CDIM + (long)BZ * Pout;
        P = Pout;
    }
}

// round 8
// speedup vs baseline: 1.2910x; 1.1028x over previous
#include <cuda_runtime.h>
#include <cuda_bf16.h>
#include <math.h>
#include <cstdint>

// ---------------------------------------------------------------------------
// TreeGetter: 11-level conv halving tree as implicit GEMM on mma.sync (bf16,
// hi/lo 3-product split for ~fp32 accuracy). M flattened = batch*P.
// 128x128x32 block, 8 warps, 64x32 warp tile, 4-stage cp.async pipeline with
// ONE __syncthreads per chunk, and full-masked M-tile skip (ragged lengths).
// ---------------------------------------------------------------------------

#define CDIM 768
#define CK   2304
#define NLEV 11
#define BZ   16
#define BM   128
#define BN   128
#define BKC  32
#define NCH  (CK / BKC)      // 72
#define STAGES 4

#define ASTRIDE 40           // bf16 elems per A row (32 + 8 pad) = 80B
#define BSTRIDE 136          // bf16 elems per B row (128 + 8 pad) = 272B
#define A_BYTES (BM * ASTRIDE * 2)               // 10240
#define B_BYTES (BKC * BSTRIDE * 2)              // 8704
#define STAGE_BYTES (2 * A_BYTES + 2 * B_BYTES)  // 37888
#define SMEM_BYTES (STAGES * STAGE_BYTES)        // 151552

// ---------------- scratch (device globals; allocation-free rule) ------------
#define MAXE ((long)BZ * 2048 * CDIM)
__device__ __nv_bfloat16 g_xhi[MAXE], g_xlo[MAXE];   // conv1 input splits
__device__ __nv_bfloat16 g_hhi[MAXE], g_hlo[MAXE];   // conv2 input splits
// weights transposed to [kg][o], kg = d*768 + i
__device__ __nv_bfloat16 g_w1hi[CK * CDIM], g_w1lo[CK * CDIM];
__device__ __nv_bfloat16 g_w2hi[CK * CDIM], g_w2lo[CK * CDIM];

__device__ __forceinline__ void split_bf16(float v, __nv_bfloat16& hi,
                                           __nv_bfloat16& lo) {
    hi = __float2bfloat16(v);
    lo = __float2bfloat16(v - __bfloat162float(hi));
}

__device__ __forceinline__ uint32_t smem_u32(const void* p) {
    uint32_t a;
    asm("{ .reg .u64 t; cvta.to.shared.u64 t, %1; cvt.u32.u64 %0, t; }"
        : "=r"(a) : "l"(p));
    return a;
}
__device__ __forceinline__ void cp_async16(uint32_t dst, const void* src,
                                           bool pred) {
    int sz = pred ? 16 : 0;
    asm volatile("cp.async.cg.shared.global [%0], [%1], 16, %2;"
                 :: "r"(dst), "l"(src), "r"(sz));
}
__device__ __forceinline__ void cp_commit() {
    asm volatile("cp.async.commit_group;");
}
__device__ __forceinline__ void ldsm_x4(uint32_t* r, uint32_t a) {
    asm volatile("ldmatrix.sync.aligned.m8n8.x4.shared.b16 {%0,%1,%2,%3}, [%4];"
                 : "=r"(r[0]), "=r"(r[1]), "=r"(r[2]), "=r"(r[3]) : "r"(a));
}
__device__ __forceinline__ void ldsm_x4_t(uint32_t* r, uint32_t a) {
    asm volatile("ldmatrix.sync.aligned.m8n8.x4.trans.shared.b16 {%0,%1,%2,%3}, [%4];"
                 : "=r"(r[0]), "=r"(r[1]), "=r"(r[2]), "=r"(r[3]) : "r"(a));
}
__device__ __forceinline__ void mma16816(float* d, const uint32_t* a,
                                         const uint32_t* b) {
    asm("mma.sync.aligned.m16n8k16.row.col.f32.bf16.bf16.f32 "
        "{%0,%1,%2,%3}, {%4,%5,%6,%7}, {%8,%9}, {%0,%1,%2,%3};"
        : "+f"(d[0]), "+f"(d[1]), "+f"(d[2]), "+f"(d[3])
        : "r"(a[0]), "r"(a[1]), "r"(a[2]), "r"(a[3]), "r"(b[0]), "r"(b[1]));
}

// ---------------------------------------------------------------------------
__global__ void prep_weights(const float* __restrict__ w1,
                             const float* __restrict__ w2) {
    int total = CK * CDIM;
    for (int j = blockIdx.x * blockDim.x + threadIdx.x; j < total;
         j += gridDim.x * blockDim.x) {
        int o  = j % CDIM;
        int kg = j / CDIM;
        int d  = kg / CDIM;
        int i  = kg - d * CDIM;
        long src = (long)o * CK + i * 3 + d;   // w[o][i][d]
        split_bf16(w1[src], g_w1hi[j], g_w1lo[j]);
        split_bf16(w2[src], g_w2hi[j], g_w2lo[j]);
    }
}

__global__ void prep_input(const float* __restrict__ seq,
                           const int* __restrict__ lengths) {
    long total = MAXE;
    for (long j = blockIdx.x * (long)blockDim.x + threadIdx.x; j < total;
         j += gridDim.x * (long)blockDim.x) {
        long bp = j / CDIM;
        int p = (int)(bp % 2048);
        int b = (int)(bp / 2048);
        float v = (p < lengths[b]) ? seq[j] : 0.f;
        split_bf16(v, g_xhi[j], g_xlo[j]);
    }
}

__global__ void mask_kernel(float* __restrict__ out,
                            const int* __restrict__ lengths) {
    int idx    = blockIdx.x * blockDim.x + threadIdx.x;
    int stride = gridDim.x * blockDim.x;
    long off = 0;
    int P = 2048;
    for (int lvl = 0; lvl < NLEV; lvl++) {
        int Pout = (P - 1) / 2 + 1;
        long maskOff = off + (long)BZ * Pout * CDIM;
        int n = BZ * Pout;
        for (int i = idx; i < n; i += stride) {
            int b = i / Pout, p = i % Pout;
            int L = lengths[b];
            for (int t = 0; t <= lvl; t++) L = (L - 1) / 2 + 1;
            out[maskOff + i] = (p < L) ? 1.f : 0.f;
        }
        off = maskOff + n;
        P = Pout;
    }
}

// ---------------------------------------------------------------------------
// Implicit-GEMM conv on mma.sync.  M rows flattened over (b, p).
// 256 threads = 8 warps (2 M x 4 N), warp tile 64x32, block 128x128x32.
template <int STRIDE, bool DO_GELU>
__global__ void __launch_bounds__(256, 1)
conv_mma(const float* __restrict__ bias, float* __restrict__ outY,
         int Pin, int Pout, const int* __restrict__ lengths, int level) {
    extern __shared__ char smem[];
    const uint32_t sbase = smem_u32(smem);
    const int tid   = threadIdx.x;
    const int lane  = tid & 31;
    const int wid   = tid >> 5;
    const int warpM = (wid & 1) * 64;
    const int warpN = (wid >> 1) * 32;
    const int p0    = blockIdx.x * BM;
    const int n0    = blockIdx.y * BN;
    const int Mtot  = BZ * Pout;

    const __nv_bfloat16* Xhi = DO_GELU ? g_xhi : g_hhi;
    const __nv_bfloat16* Xlo = DO_GELU ? g_xlo : g_hlo;
    const __nv_bfloat16* Whi = DO_GELU ? g_w1hi : g_w2hi;
    const __nv_bfloat16* Wlo = DO_GELU ? g_w1lo : g_w2lo;

    float acc[4][4][4];
#pragma unroll
    for (int a = 0; a < 4; a++)
#pragma unroll
        for (int b = 0; b < 4; b++)
#pragma unroll
            for (int c = 0; c < 4; c++) acc[a][b][c] = 0.f;

    // ---- full-masked tile skip: any valid output row in [p0, p0+BM)? ----
    bool anyValid = false;
    {
        int bA = p0 / Pout;
        int bB = (p0 + BM - 1) / Pout;
        if (bB >= BZ) bB = BZ - 1;
        for (int b = bA; b <= bB; b++) {
            int L = lengths[b];
            for (int t = 0; t < level; t++) L = (L - 1) / 2 + 1;
            int lenOut = DO_GELU ? L : ((L - 1) / 2 + 1);
            int pstart = p0 > b * Pout ? p0 - b * Pout : 0;
            if (pstart < lenOut) { anyValid = true; break; }
        }
    }

    if (anyValid) {
        // ---- per-thread load geometry (fixed across stages) ----
        int aPosB[2]; long aRowBase[2]; bool aOk[2];
        const int akc = tid & 3;
#pragma unroll
        for (int i = 0; i < 2; i++) {
            int r = (tid + i * 256) >> 2;
            int grow = p0 + r;
            bool ok = grow < Mtot;
            int b = ok ? grow / Pout : 0;
            int p = grow - b * Pout;
            aOk[i] = ok;
            aPosB[i] = p * STRIDE - 1;
            aRowBase[i] = (long)b * Pin;
        }
        const int bkrow0 = tid >> 4;
        const int bnc = tid & 15;

        auto load_stage = [&](int slot, int it) {
            const uint32_t sa = sbase + slot * STAGE_BYTES;
            const int kk = it * BKC;
            const int d  = (kk >= 1536) ? 2 : (kk >= 768 ? 1 : 0);
            const int c0 = kk - d * CDIM;
#pragma unroll
            for (int i = 0; i < 2; i++) {
                int id  = tid + i * 256;
                int row = id >> 2;
                int pos = aPosB[i] + d;
                bool v = aOk[i] && pos >= 0 && pos < Pin;
                long g = v ? ((aRowBase[i] + pos) * CDIM + c0 + akc * 8) : 0;
                uint32_t dst = sa + (row * ASTRIDE + akc * 8) * 2;
                cp_async16(dst, Xhi + g, v);
                cp_async16(dst + A_BYTES, Xlo + g, v);
            }
#pragma unroll
            for (int i = 0; i < 2; i++) {
                int krow = bkrow0 + i * 16;
                long g = (long)(kk + krow) * CDIM + n0 + bnc * 8;
                uint32_t dst = sa + 2 * A_BYTES + (krow * BSTRIDE + bnc * 8) * 2;
                cp_async16(dst, Whi + g, true);
                cp_async16(dst + B_BYTES, Wlo + g, true);
            }
            cp_commit();
        };

        // ldmatrix per-lane offsets (bytes)
        const uint32_t aoff =
            ((warpM + (lane & 15)) * ASTRIDE + ((lane >> 4) << 3)) * 2;
        const uint32_t boff =
            ((lane & 15) * BSTRIDE + warpN + ((lane >> 4) << 3)) * 2;

        // ---- pipeline: 4 stages, prefetch depth 3, single sync per chunk ----
        load_stage(0, 0);
        load_stage(1, 1);
        load_stage(2, 2);

#pragma unroll 1
        for (int it = 0; it < NCH; it++) {
            asm volatile("cp.async.wait_group %0;" :: "n"(2));
            __syncthreads();
            int pre = it + 3;
            if (pre < NCH) load_stage(pre & 3, pre);
            else cp_commit();   // keep group count uniform

            const uint32_t sa = sbase + (it & 3) * STAGE_BYTES;
            const uint32_t aaddr = sa + aoff;
            const uint32_t baddr = sa + 2 * A_BYTES + boff;
#pragma unroll
            for (int ks2 = 0; ks2 < 2; ks2++) {
                const int ks = ks2 * 16;
                uint32_t ah[4][4], al[4][4], bh[2][4], bl[2][4];
#pragma unroll
                for (int mt = 0; mt < 4; mt++) {
                    ldsm_x4(ah[mt], aaddr + (mt * 16 * ASTRIDE + ks) * 2);
                    ldsm_x4(al[mt], aaddr + A_BYTES + (mt * 16 * ASTRIDE + ks) * 2);
                }
#pragma unroll
                for (int np = 0; np < 2; np++) {
                    ldsm_x4_t(bh[np], baddr + (ks * BSTRIDE + np * 16) * 2);
                    ldsm_x4_t(bl[np], baddr + B_BYTES + (ks * BSTRIDE + np * 16) * 2);
                }
#pragma unroll
                for (int mt = 0; mt < 4; mt++)
#pragma unroll
                    for (int nt = 0; nt < 4; nt++) {
                        const uint32_t* h = &bh[nt >> 1][(nt & 1) * 2];
                        const uint32_t* l = &bl[nt >> 1][(nt & 1) * 2];
                        mma16816(acc[mt][nt], ah[mt], h);
                        mma16816(acc[mt][nt], ah[mt], l);
                        mma16816(acc[mt][nt], al[mt], h);
                    }
            }
        }
    }

    // ---- epilogue (also writes zeros for skipped/masked rows) ----
    const int mrow0 = p0 + warpM + (lane >> 2);
    const int colb  = n0 + warpN + 2 * (lane & 3);
#pragma unroll
    for (int mt = 0; mt < 4; mt++) {
#pragma unroll
        for (int half = 0; half < 2; half++) {
            int row = mrow0 + mt * 16 + half * 8;
            if (row >= Mtot) continue;
            int b = row / Pout;
            int p = row - b * Pout;
            int L = lengths[b];
            for (int t = 0; t < level; t++) L = (L - 1) / 2 + 1;
            int lenOut = DO_GELU ? L : ((L - 1) / 2 + 1);
            bool valid = (p < lenOut) && anyValid;
            long base = (long)row * CDIM;
#pragma unroll
            for (int nt = 0; nt < 4; nt++) {
                int col = colb + nt * 8;
                float z0 = 0.f, z1 = 0.f;
                if (valid) {
                    z0 = acc[mt][nt][half * 2 + 0] + __ldg(&bias[col]);
                    z1 = acc[mt][nt][half * 2 + 1] + __ldg(&bias[col + 1]);
                    if (DO_GELU) {
                        z0 = 0.5f * z0 * (1.f + erff(z0 * 0.70710678118654752f));
                        z1 = 0.5f * z1 * (1.f + erff(z1 * 0.70710678118654752f));
                    }
                }
                __nv_bfloat162 h2, l2;
                split_bf16(z0, h2.x, l2.x);
                split_bf16(z1, h2.y, l2.y);
                if (DO_GELU) {
                    *(__nv_bfloat162*)(g_hhi + base + col) = h2;
                    *(__nv_bfloat162*)(g_hlo + base + col) = l2;
                } else {
                    float2 o2 = make_float2(z0, z1);
                    *(float2*)(outY + base + col) = o2;
                    *(__nv_bfloat162*)(g_xhi + base + col) = h2;
                    *(__nv_bfloat162*)(g_xlo + base + col) = l2;
                }
            }
        }
    }
}

// ---------------------------------------------------------------------------
extern "C" void kernel_launch(void* const* d_in, const int* in_sizes, int n_in,
                              void* d_out, int out_size) {
    const float* seq     = (const float*)d_in[0];
    const int*   lengths = (const int*)  d_in[1];
    const float* w1      = (const float*)d_in[2];
    const float* b1      = (const float*)d_in[3];
    const float* w2      = (const float*)d_in[4];
    const float* b2      = (const float*)d_in[5];
    float* out = (float*)d_out;

    cudaFuncSetAttribute(conv_mma<1, true>,
                         cudaFuncAttributeMaxDynamicSharedMemorySize, SMEM_BYTES);
    cudaFuncSetAttribute(conv_mma<2, false>,
                         cudaFuncAttributeMaxDynamicSharedMemorySize, SMEM_BYTES);

    prep_weights<<<256, 256>>>(w1, w2);
    prep_input<<<512, 256>>>(seq, lengths);
    mask_kernel<<<64, 256>>>(out, lengths);

    int P = 2048;
    long off = 0;
    for (int lvl = 0; lvl < NLEV; lvl++) {
        int Pout = (P - 1) / 2 + 1;
        dim3 g1((BZ * P + BM - 1) / BM, CDIM / BN);
        conv_mma<1, true><<<g1, 256, SMEM_BYTES>>>(b1, nullptr, P, P,
                                                   lengths, lvl);
        dim3 g2((BZ * Pout + BM - 1) / BM, CDIM / BN);
        conv_mma<2, false><<<g2, 256, SMEM_BYTES>>>(b2, out + off, P, Pout,
                                                    lengths, lvl);
        off += (long)BZ * Pout * CDIM + (long)BZ * Pout;
        P = Pout;
    }
}

// round 9
// speedup vs baseline: 1.3144x; 1.0181x over previous
#include <cuda_runtime.h>
#include <cuda_bf16.h>
#include <math.h>
#include <cstdint>

// ---------------------------------------------------------------------------
// TreeGetter: 11-level conv halving tree as implicit GEMM on mma.sync (bf16,
// hi/lo 3-product split). 128x128x32 block, 8 warps, 64x32 warp tile,
// 4-stage cp.async pipeline + register fragment double-buffering: ldsm of one
// half-chunk overlaps mma of the other, barrier hoisted between mma halves.
// Full-masked M-tile skip for ragged lengths.
// ---------------------------------------------------------------------------

#define CDIM 768
#define CK   2304
#define NLEV 11
#define BZ   16
#define BM   128
#define BN   128
#define BKC  32
#define NCH  (CK / BKC)      // 72
#define STAGES 4

#define ASTRIDE 40           // bf16 elems per A row (32 + 8 pad) = 80B
#define BSTRIDE 136          // bf16 elems per B row (128 + 8 pad) = 272B
#define A_BYTES (BM * ASTRIDE * 2)               // 10240
#define B_BYTES (BKC * BSTRIDE * 2)              // 8704
#define STAGE_BYTES (2 * A_BYTES + 2 * B_BYTES)  // 37888
#define SMEM_BYTES (STAGES * STAGE_BYTES)        // 151552

// ---------------- scratch (device globals; allocation-free rule) ------------
#define MAXE ((long)BZ * 2048 * CDIM)
__device__ __nv_bfloat16 g_xhi[MAXE], g_xlo[MAXE];   // conv1 input splits
__device__ __nv_bfloat16 g_hhi[MAXE], g_hlo[MAXE];   // conv2 input splits
__device__ __nv_bfloat16 g_w1hi[CK * CDIM], g_w1lo[CK * CDIM];
__device__ __nv_bfloat16 g_w2hi[CK * CDIM], g_w2lo[CK * CDIM];

__device__ __forceinline__ void split_bf16(float v, __nv_bfloat16& hi,
                                           __nv_bfloat16& lo) {
    hi = __float2bfloat16(v);
    lo = __float2bfloat16(v - __bfloat162float(hi));
}

__device__ __forceinline__ uint32_t smem_u32(const void* p) {
    uint32_t a;
    asm("{ .reg .u64 t; cvta.to.shared.u64 t, %1; cvt.u32.u64 %0, t; }"
        : "=r"(a) : "l"(p));
    return a;
}
__device__ __forceinline__ void cp_async16(uint32_t dst, const void* src,
                                           bool pred) {
    int sz = pred ? 16 : 0;
    asm volatile("cp.async.cg.shared.global [%0], [%1], 16, %2;"
                 :: "r"(dst), "l"(src), "r"(sz));
}
__device__ __forceinline__ void cp_commit() {
    asm volatile("cp.async.commit_group;");
}
__device__ __forceinline__ void ldsm_x4(uint32_t* r, uint32_t a) {
    asm volatile("ldmatrix.sync.aligned.m8n8.x4.shared.b16 {%0,%1,%2,%3}, [%4];"
                 : "=r"(r[0]), "=r"(r[1]), "=r"(r[2]), "=r"(r[3]) : "r"(a));
}
__device__ __forceinline__ void ldsm_x4_t(uint32_t* r, uint32_t a) {
    asm volatile("ldmatrix.sync.aligned.m8n8.x4.trans.shared.b16 {%0,%1,%2,%3}, [%4];"
                 : "=r"(r[0]), "=r"(r[1]), "=r"(r[2]), "=r"(r[3]) : "r"(a));
}
__device__ __forceinline__ void mma16816(float* d, const uint32_t* a,
                                         const uint32_t* b) {
    asm("mma.sync.aligned.m16n8k16.row.col.f32.bf16.bf16.f32 "
        "{%0,%1,%2,%3}, {%4,%5,%6,%7}, {%8,%9}, {%0,%1,%2,%3};"
        : "+f"(d[0]), "+f"(d[1]), "+f"(d[2]), "+f"(d[3])
        : "r"(a[0]), "r"(a[1]), "r"(a[2]), "r"(a[3]), "r"(b[0]), "r"(b[1]));
}

// ---------------------------------------------------------------------------
__global__ void prep_weights(const float* __restrict__ w1,
                             const float* __restrict__ w2) {
    int total = CK * CDIM;
    for (int j = blockIdx.x * blockDim.x + threadIdx.x; j < total;
         j += gridDim.x * blockDim.x) {
        int o  = j % CDIM;
        int kg = j / CDIM;
        int d  = kg / CDIM;
        int i  = kg - d * CDIM;
        long src = (long)o * CK + i * 3 + d;   // w[o][i][d]
        split_bf16(w1[src], g_w1hi[j], g_w1lo[j]);
        split_bf16(w2[src], g_w2hi[j], g_w2lo[j]);
    }
}

__global__ void prep_input(const float* __restrict__ seq,
                           const int* __restrict__ lengths) {
    long total = MAXE;
    for (long j = blockIdx.x * (long)blockDim.x + threadIdx.x; j < total;
         j += gridDim.x * (long)blockDim.x) {
        long bp = j / CDIM;
        int p = (int)(bp % 2048);
        int b = (int)(bp / 2048);
        float v = (p < lengths[b]) ? seq[j] : 0.f;
        split_bf16(v, g_xhi[j], g_xlo[j]);
    }
}

__global__ void mask_kernel(float* __restrict__ out,
                            const int* __restrict__ lengths) {
    int idx    = blockIdx.x * blockDim.x + threadIdx.x;
    int stride = gridDim.x * blockDim.x;
    long off = 0;
    int P = 2048;
    for (int lvl = 0; lvl < NLEV; lvl++) {
        int Pout = (P - 1) / 2 + 1;
        long maskOff = off + (long)BZ * Pout * CDIM;
        int n = BZ * Pout;
        for (int i = idx; i < n; i += stride) {
            int b = i / Pout, p = i % Pout;
            int L = lengths[b];
            for (int t = 0; t <= lvl; t++) L = (L - 1) / 2 + 1;
            out[maskOff + i] = (p < L) ? 1.f : 0.f;
        }
        off = maskOff + n;
        P = Pout;
    }
}

// ---------------------------------------------------------------------------
// Implicit-GEMM conv on mma.sync with fragment double-buffering.
template <int STRIDE, bool DO_GELU>
__global__ void __launch_bounds__(256, 1)
conv_mma(const float* __restrict__ bias, float* __restrict__ outY,
         int Pin, int Pout, const int* __restrict__ lengths, int level) {
    extern __shared__ char smem[];
    const uint32_t sbase = smem_u32(smem);
    const int tid   = threadIdx.x;
    const int lane  = tid & 31;
    const int wid   = tid >> 5;
    const int warpM = (wid & 1) * 64;
    const int warpN = (wid >> 1) * 32;
    const int p0    = blockIdx.x * BM;
    const int n0    = blockIdx.y * BN;
    const int Mtot  = BZ * Pout;

    const __nv_bfloat16* Xhi = DO_GELU ? g_xhi : g_hhi;
    const __nv_bfloat16* Xlo = DO_GELU ? g_xlo : g_hlo;
    const __nv_bfloat16* Whi = DO_GELU ? g_w1hi : g_w2hi;
    const __nv_bfloat16* Wlo = DO_GELU ? g_w1lo : g_w2lo;

    float acc[4][4][4];
#pragma unroll
    for (int a = 0; a < 4; a++)
#pragma unroll
        for (int b = 0; b < 4; b++)
#pragma unroll
            for (int c = 0; c < 4; c++) acc[a][b][c] = 0.f;

    // ---- full-masked tile skip ----
    bool anyValid = false;
    {
        int bA = p0 / Pout;
        int bB = (p0 + BM - 1) / Pout;
        if (bB >= BZ) bB = BZ - 1;
        for (int b = bA; b <= bB; b++) {
            int L = lengths[b];
            for (int t = 0; t < level; t++) L = (L - 1) / 2 + 1;
            int lenOut = DO_GELU ? L : ((L - 1) / 2 + 1);
            int pstart = p0 > b * Pout ? p0 - b * Pout : 0;
            if (pstart < lenOut) { anyValid = true; break; }
        }
    }

    if (anyValid) {
        // ---- per-thread load geometry ----
        int aPosB[2]; long aRowBase[2]; bool aOk[2];
        const int akc = tid & 3;
#pragma unroll
        for (int i = 0; i < 2; i++) {
            int r = (tid + i * 256) >> 2;
            int grow = p0 + r;
            bool ok = grow < Mtot;
            int b = ok ? grow / Pout : 0;
            int p = grow - b * Pout;
            aOk[i] = ok;
            aPosB[i] = p * STRIDE - 1;
            aRowBase[i] = (long)b * Pin;
        }
        const int bkrow0 = tid >> 4;
        const int bnc = tid & 15;

        auto load_stage = [&](int slot, int it) {
            const uint32_t sa = sbase + slot * STAGE_BYTES;
            const int kk = it * BKC;
            const int d  = (kk >= 1536) ? 2 : (kk >= 768 ? 1 : 0);
            const int c0 = kk - d * CDIM;
#pragma unroll
            for (int i = 0; i < 2; i++) {
                int id  = tid + i * 256;
                int row = id >> 2;
                int pos = aPosB[i] + d;
                bool v = aOk[i] && pos >= 0 && pos < Pin;
                long g = v ? ((aRowBase[i] + pos) * CDIM + c0 + akc * 8) : 0;
                uint32_t dst = sa + (row * ASTRIDE + akc * 8) * 2;
                cp_async16(dst, Xhi + g, v);
                cp_async16(dst + A_BYTES, Xlo + g, v);
            }
#pragma unroll
            for (int i = 0; i < 2; i++) {
                int krow = bkrow0 + i * 16;
                long g = (long)(kk + krow) * CDIM + n0 + bnc * 8;
                uint32_t dst = sa + 2 * A_BYTES + (krow * BSTRIDE + bnc * 8) * 2;
                cp_async16(dst, Whi + g, true);
                cp_async16(dst + B_BYTES, Wlo + g, true);
            }
            cp_commit();
        };

        // ldmatrix per-lane offsets (bytes)
        const uint32_t aoff =
            ((warpM + (lane & 15)) * ASTRIDE + ((lane >> 4) << 3)) * 2;
        const uint32_t boff =
            ((lane & 15) * BSTRIDE + warpN + ((lane >> 4) << 3)) * 2;

        // fragment double buffer (set 0 / set 1)
        uint32_t ah[2][4][4], al[2][4][4], bh[2][2][4], bl[2][2][4];

        auto ldsm_half = [&](int s, uint32_t sa, int ks) {
            const uint32_t aaddr = sa + aoff;
            const uint32_t baddr = sa + 2 * A_BYTES + boff;
#pragma unroll
            for (int mt = 0; mt < 4; mt++) {
                ldsm_x4(ah[s][mt], aaddr + (mt * 16 * ASTRIDE + ks) * 2);
                ldsm_x4(al[s][mt], aaddr + A_BYTES + (mt * 16 * ASTRIDE + ks) * 2);
            }
#pragma unroll
            for (int np = 0; np < 2; np++) {
                ldsm_x4_t(bh[s][np], baddr + (ks * BSTRIDE + np * 16) * 2);
                ldsm_x4_t(bl[s][np], baddr + B_BYTES + (ks * BSTRIDE + np * 16) * 2);
            }
        };
        auto mma_half = [&](int s) {
#pragma unroll
            for (int mt = 0; mt < 4; mt++)
#pragma unroll
                for (int nt = 0; nt < 4; nt++)
                    mma16816(acc[mt][nt], ah[s][mt], &bh[s][nt >> 1][(nt & 1) * 2]);
#pragma unroll
            for (int mt = 0; mt < 4; mt++)
#pragma unroll
                for (int nt = 0; nt < 4; nt++)
                    mma16816(acc[mt][nt], ah[s][mt], &bl[s][nt >> 1][(nt & 1) * 2]);
#pragma unroll
            for (int mt = 0; mt < 4; mt++)
#pragma unroll
                for (int nt = 0; nt < 4; nt++)
                    mma16816(acc[mt][nt], al[s][mt], &bh[s][nt >> 1][(nt & 1) * 2]);
        };

        // ---- prologue ----
        load_stage(0, 0);
        load_stage(1, 1);
        load_stage(2, 2);
        asm volatile("cp.async.wait_group %0;" :: "n"(2));
        __syncthreads();
        ldsm_half(0, sbase, 0);   // chunk 0, first half

        // ---- main loop: ldsm(set1) ‖ mma(set0); next-chunk barrier + ldsm
        //      hoisted between the two mma halves ----
#pragma unroll 1
        for (int it = 0; it < NCH; it++) {
            const uint32_t sa = sbase + (it & 3) * STAGE_BYTES;
            ldsm_half(1, sa, 16);      // second half of current chunk
            mma_half(0);               // overlaps the ldsm above
            if (it + 1 < NCH) {
                asm volatile("cp.async.wait_group %0;" :: "n"(1));
                __syncthreads();
                if (it + 3 < NCH) load_stage((it + 3) & 3, it + 3);
                ldsm_half(0, sbase + ((it + 1) & 3) * STAGE_BYTES, 0);
            }
            mma_half(1);               // overlaps next chunk's ldsm/cp.async
        }
    }

    // ---- epilogue (also writes zeros for skipped/masked rows) ----
    const int mrow0 = p0 + warpM + (lane >> 2);
    const int colb  = n0 + warpN + 2 * (lane & 3);
#pragma unroll
    for (int mt = 0; mt < 4; mt++) {
#pragma unroll
        for (int half = 0; half < 2; half++) {
            int row = mrow0 + mt * 16 + half * 8;
            if (row >= Mtot) continue;
            int b = row / Pout;
            int p = row - b * Pout;
            int L = lengths[b];
            for (int t = 0; t < level; t++) L = (L - 1) / 2 + 1;
            int lenOut = DO_GELU ? L : ((L - 1) / 2 + 1);
            bool valid = (p < lenOut) && anyValid;
            long base = (long)row * CDIM;
#pragma unroll
            for (int nt = 0; nt < 4; nt++) {
                int col = colb + nt * 8;
                float z0 = 0.f, z1 = 0.f;
                if (valid) {
                    z0 = acc[mt][nt][half * 2 + 0] + __ldg(&bias[col]);
                    z1 = acc[mt][nt][half * 2 + 1] + __ldg(&bias[col + 1]);
                    if (DO_GELU) {
                        z0 = 0.5f * z0 * (1.f + erff(z0 * 0.70710678118654752f));
                        z1 = 0.5f * z1 * (1.f + erff(z1 * 0.70710678118654752f));
                    }
                }
                __nv_bfloat162 h2, l2;
                split_bf16(z0, h2.x, l2.x);
                split_bf16(z1, h2.y, l2.y);
                if (DO_GELU) {
                    *(__nv_bfloat162*)(g_hhi + base + col) = h2;
                    *(__nv_bfloat162*)(g_hlo + base + col) = l2;
                } else {
                    float2 o2 = make_float2(z0, z1);
                    *(float2*)(outY + base + col) = o2;
                    *(__nv_bfloat162*)(g_xhi + base + col) = h2;
                    *(__nv_bfloat162*)(g_xlo + base + col) = l2;
                }
            }
        }
    }
}

// ---------------------------------------------------------------------------
extern "C" void kernel_launch(void* const* d_in, const int* in_sizes, int n_in,
                              void* d_out, int out_size) {
    const float* seq     = (const float*)d_in[0];
    const int*   lengths = (const int*)  d_in[1];
    const float* w1      = (const float*)d_in[2];
    const float* b1      = (const float*)d_in[3];
    const float* w2      = (const float*)d_in[4];
    const float* b2      = (const float*)d_in[5];
    float* out = (float*)d_out;

    cudaFuncSetAttribute(conv_mma<1, true>,
                         cudaFuncAttributeMaxDynamicSharedMemorySize, SMEM_BYTES);
    cudaFuncSetAttribute(conv_mma<2, false>,
                         cudaFuncAttributeMaxDynamicSharedMemorySize, SMEM_BYTES);

    prep_weights<<<256, 256>>>(w1, w2);
    prep_input<<<512, 256>>>(seq, lengths);
    mask_kernel<<<64, 256>>>(out, lengths);

    int P = 2048;
    long off = 0;
    for (int lvl = 0; lvl < NLEV; lvl++) {
        int Pout = (P - 1) / 2 + 1;
        dim3 g1((BZ * P + BM - 1) / BM, CDIM / BN);
        conv_mma<1, true><<<g1, 256, SMEM_BYTES>>>(b1, nullptr, P, P,
                                                   lengths, lvl);
        dim3 g2((BZ * Pout + BM - 1) / BM, CDIM / BN);
        conv_mma<2, false><<<g2, 256, SMEM_BYTES>>>(b2, out + off, P, Pout,
                                                    lengths, lvl);
        off += (long)BZ * Pout * CDIM + (long)BZ * Pout;
        P = Pout;
    }
}

// round 10
// speedup vs baseline: 1.6698x; 1.2704x over previous
#include <cuda_runtime.h>
#include <cuda_bf16.h>
#include <math.h>
#include <cstdint>

// ---------------------------------------------------------------------------
// TreeGetter: 11-level conv halving tree as implicit GEMM on mma.sync (bf16,
// hi/lo 3-product split). 128x128x32 block, 8 warps, 64x32 warp tile, 4-stage
// cp.async pipeline + fragment double-buffering. Full-masked M-tile skip.
// NEW: split-K (by conv tap, 3 ways) for latency-bound levels (M <= 4096):
// partials to fp32 workspace + tiny reduce kernel (bias/gelu/mask/split).
// ---------------------------------------------------------------------------

#define CDIM 768
#define CK   2304
#define NLEV 11
#define BZ   16
#define BM   128
#define BN   128
#define BKC  32
#define NCH  (CK / BKC)      // 72
#define NSPL 3
#define CH_PER_SPL (NCH / NSPL)   // 24
#define SPLIT_MAX_M 4096

#define ASTRIDE 40           // bf16 elems per A row (32 + 8 pad) = 80B
#define BSTRIDE 136          // bf16 elems per B row (128 + 8 pad) = 272B
#define A_BYTES (BM * ASTRIDE * 2)               // 10240
#define B_BYTES (BKC * BSTRIDE * 2)              // 8704
#define STAGE_BYTES (2 * A_BYTES + 2 * B_BYTES)  // 37888
#define SMEM_BYTES (4 * STAGE_BYTES)             // 151552

// ---------------- scratch (device globals; allocation-free rule) ------------
#define MAXE ((long)BZ * 2048 * CDIM)
__device__ __nv_bfloat16 g_xhi[MAXE], g_xlo[MAXE];   // conv1 input splits
__device__ __nv_bfloat16 g_hhi[MAXE], g_hlo[MAXE];   // conv2 input splits
__device__ __nv_bfloat16 g_w1hi[CK * CDIM], g_w1lo[CK * CDIM];
__device__ __nv_bfloat16 g_w2hi[CK * CDIM], g_w2lo[CK * CDIM];
__device__ float g_part[(long)NSPL * SPLIT_MAX_M * CDIM];   // split-K partials

__device__ __forceinline__ void split_bf16(float v, __nv_bfloat16& hi,
                                           __nv_bfloat16& lo) {
    hi = __float2bfloat16(v);
    lo = __float2bfloat16(v - __bfloat162float(hi));
}

__device__ __forceinline__ uint32_t smem_u32(const void* p) {
    uint32_t a;
    asm("{ .reg .u64 t; cvta.to.shared.u64 t, %1; cvt.u32.u64 %0, t; }"
        : "=r"(a) : "l"(p));
    return a;
}
__device__ __forceinline__ void cp_async16(uint32_t dst, const void* src,
                                           bool pred) {
    int sz = pred ? 16 : 0;
    asm volatile("cp.async.cg.shared.global [%0], [%1], 16, %2;"
                 :: "r"(dst), "l"(src), "r"(sz));
}
__device__ __forceinline__ void cp_commit() {
    asm volatile("cp.async.commit_group;");
}
__device__ __forceinline__ void ldsm_x4(uint32_t* r, uint32_t a) {
    asm volatile("ldmatrix.sync.aligned.m8n8.x4.shared.b16 {%0,%1,%2,%3}, [%4];"
                 : "=r"(r[0]), "=r"(r[1]), "=r"(r[2]), "=r"(r[3]) : "r"(a));
}
__device__ __forceinline__ void ldsm_x4_t(uint32_t* r, uint32_t a) {
    asm volatile("ldmatrix.sync.aligned.m8n8.x4.trans.shared.b16 {%0,%1,%2,%3}, [%4];"
                 : "=r"(r[0]), "=r"(r[1]), "=r"(r[2]), "=r"(r[3]) : "r"(a));
}
__device__ __forceinline__ void mma16816(float* d, const uint32_t* a,
                                         const uint32_t* b) {
    asm("mma.sync.aligned.m16n8k16.row.col.f32.bf16.bf16.f32 "
        "{%0,%1,%2,%3}, {%4,%5,%6,%7}, {%8,%9}, {%0,%1,%2,%3};"
        : "+f"(d[0]), "+f"(d[1]), "+f"(d[2]), "+f"(d[3])
        : "r"(a[0]), "r"(a[1]), "r"(a[2]), "r"(a[3]), "r"(b[0]), "r"(b[1]));
}
__device__ __forceinline__ float gelu_exact(float z) {
    return 0.5f * z * (1.f + erff(z * 0.70710678118654752f));
}

// ---------------------------------------------------------------------------
__global__ void prep_weights(const float* __restrict__ w1,
                             const float* __restrict__ w2) {
    int total = CK * CDIM;
    for (int j = blockIdx.x * blockDim.x + threadIdx.x; j < total;
         j += gridDim.x * blockDim.x) {
        int o  = j % CDIM;
        int kg = j / CDIM;
        int d  = kg / CDIM;
        int i  = kg - d * CDIM;
        long src = (long)o * CK + i * 3 + d;   // w[o][i][d]
        split_bf16(w1[src], g_w1hi[j], g_w1lo[j]);
        split_bf16(w2[src], g_w2hi[j], g_w2lo[j]);
    }
}

__global__ void prep_input(const float* __restrict__ seq,
                           const int* __restrict__ lengths) {
    long total = MAXE;
    for (long j = blockIdx.x * (long)blockDim.x + threadIdx.x; j < total;
         j += gridDim.x * (long)blockDim.x) {
        long bp = j / CDIM;
        int p = (int)(bp % 2048);
        int b = (int)(bp / 2048);
        float v = (p < lengths[b]) ? seq[j] : 0.f;
        split_bf16(v, g_xhi[j], g_xlo[j]);
    }
}

__global__ void mask_kernel(float* __restrict__ out,
                            const int* __restrict__ lengths) {
    int idx    = blockIdx.x * blockDim.x + threadIdx.x;
    int stride = gridDim.x * blockDim.x;
    long off = 0;
    int P = 2048;
    for (int lvl = 0; lvl < NLEV; lvl++) {
        int Pout = (P - 1) / 2 + 1;
        long maskOff = off + (long)BZ * Pout * CDIM;
        int n = BZ * Pout;
        for (int i = idx; i < n; i += stride) {
            int b = i / Pout, p = i % Pout;
            int L = lengths[b];
            for (int t = 0; t <= lvl; t++) L = (L - 1) / 2 + 1;
            out[maskOff + i] = (p < L) ? 1.f : 0.f;
        }
        off = maskOff + n;
        P = Pout;
    }
}

// ---------------------------------------------------------------------------
// reduce for split-K: sum 3 planes + bias (+gelu) + mask, write bf16 splits.
template <bool DO_GELU>
__global__ void reduce_split(const float* __restrict__ bias,
                             float* __restrict__ outY, int Pout,
                             const int* __restrict__ lengths, int level,
                             int Mtot) {
    long total = (long)Mtot * (CDIM / 2);
    long plane = (long)Mtot * CDIM;
    for (long i = blockIdx.x * (long)blockDim.x + threadIdx.x; i < total;
         i += gridDim.x * (long)blockDim.x) {
        int row = (int)(i / (CDIM / 2));
        int col = (int)(i % (CDIM / 2)) * 2;
        int b = row / Pout, p = row - b * Pout;
        int L = lengths[b];
        for (int t = 0; t < level; t++) L = (L - 1) / 2 + 1;
        int lenOut = DO_GELU ? L : ((L - 1) / 2 + 1);
        float z0 = 0.f, z1 = 0.f;
        if (p < lenOut) {
            long off = (long)row * CDIM + col;
            float2 v0 = *(const float2*)(g_part + off);
            float2 v1 = *(const float2*)(g_part + plane + off);
            float2 v2 = *(const float2*)(g_part + 2 * plane + off);
            z0 = v0.x + v1.x + v2.x + __ldg(&bias[col]);
            z1 = v0.y + v1.y + v2.y + __ldg(&bias[col + 1]);
            if (DO_GELU) { z0 = gelu_exact(z0); z1 = gelu_exact(z1); }
        }
        __nv_bfloat162 h2, l2;
        split_bf16(z0, h2.x, l2.x);
        split_bf16(z1, h2.y, l2.y);
        long base = (long)row * CDIM + col;
        if (DO_GELU) {
            *(__nv_bfloat162*)(g_hhi + base) = h2;
            *(__nv_bfloat162*)(g_hlo + base) = l2;
        } else {
            *(float2*)(outY + base) = make_float2(z0, z1);
            *(__nv_bfloat162*)(g_xhi + base) = h2;
            *(__nv_bfloat162*)(g_xlo + base) = l2;
        }
    }
}

// ---------------------------------------------------------------------------
// Implicit-GEMM conv on mma.sync with fragment double-buffering.
// SPLITK: blockIdx.z = tap index, 24 chunks, raw partials to g_part.
template <int STRIDE, bool DO_GELU, bool SPLITK>
__global__ void __launch_bounds__(256, 1)
conv_mma(const float* __restrict__ bias, float* __restrict__ outY,
         int Pin, int Pout, const int* __restrict__ lengths, int level) {
    extern __shared__ char smem[];
    const uint32_t sbase = smem_u32(smem);
    const int tid   = threadIdx.x;
    const int lane  = tid & 31;
    const int wid   = tid >> 5;
    const int warpM = (wid & 1) * 64;
    const int warpN = (wid >> 1) * 32;
    const int p0    = blockIdx.x * BM;
    const int n0    = blockIdx.y * BN;
    const int Mtot  = BZ * Pout;
    const int zspl  = SPLITK ? blockIdx.z : 0;
    const int itBase = zspl * CH_PER_SPL;
    const int NC     = SPLITK ? CH_PER_SPL : NCH;

    const __nv_bfloat16* Xhi = DO_GELU ? g_xhi : g_hhi;
    const __nv_bfloat16* Xlo = DO_GELU ? g_xlo : g_hlo;
    const __nv_bfloat16* Whi = DO_GELU ? g_w1hi : g_w2hi;
    const __nv_bfloat16* Wlo = DO_GELU ? g_w1lo : g_w2lo;

    float acc[4][4][4];
#pragma unroll
    for (int a = 0; a < 4; a++)
#pragma unroll
        for (int b = 0; b < 4; b++)
#pragma unroll
            for (int c = 0; c < 4; c++) acc[a][b][c] = 0.f;

    // ---- full-masked tile skip ----
    bool anyValid = false;
    {
        int bA = p0 / Pout;
        int bB = (p0 + BM - 1) / Pout;
        if (bB >= BZ) bB = BZ - 1;
        for (int b = bA; b <= bB; b++) {
            int L = lengths[b];
            for (int t = 0; t < level; t++) L = (L - 1) / 2 + 1;
            int lenOut = DO_GELU ? L : ((L - 1) / 2 + 1);
            int pstart = p0 > b * Pout ? p0 - b * Pout : 0;
            if (pstart < lenOut) { anyValid = true; break; }
        }
    }

    if (anyValid) {
        // ---- per-thread load geometry ----
        int aPosB[2]; long aRowBase[2]; bool aOk[2];
        const int akc = tid & 3;
#pragma unroll
        for (int i = 0; i < 2; i++) {
            int r = (tid + i * 256) >> 2;
            int grow = p0 + r;
            bool ok = grow < Mtot;
            int b = ok ? grow / Pout : 0;
            int p = grow - b * Pout;
            aOk[i] = ok;
            aPosB[i] = p * STRIDE - 1;
            aRowBase[i] = (long)b * Pin;
        }
        const int bkrow0 = tid >> 4;
        const int bnc = tid & 15;

        auto load_stage = [&](int slot, int it) {
            const uint32_t sa = sbase + slot * STAGE_BYTES;
            const int kk = it * BKC;
            const int d  = (kk >= 1536) ? 2 : (kk >= 768 ? 1 : 0);
            const int c0 = kk - d * CDIM;
#pragma unroll
            for (int i = 0; i < 2; i++) {
                int id  = tid + i * 256;
                int row = id >> 2;
                int pos = aPosB[i] + d;
                bool v = aOk[i] && pos >= 0 && pos < Pin;
                long g = v ? ((aRowBase[i] + pos) * CDIM + c0 + akc * 8) : 0;
                uint32_t dst = sa + (row * ASTRIDE + akc * 8) * 2;
                cp_async16(dst, Xhi + g, v);
                cp_async16(dst + A_BYTES, Xlo + g, v);
            }
#pragma unroll
            for (int i = 0; i < 2; i++) {
                int krow = bkrow0 + i * 16;
                long g = (long)(kk + krow) * CDIM + n0 + bnc * 8;
                uint32_t dst = sa + 2 * A_BYTES + (krow * BSTRIDE + bnc * 8) * 2;
                cp_async16(dst, Whi + g, true);
                cp_async16(dst + B_BYTES, Wlo + g, true);
            }
            cp_commit();
        };

        const uint32_t aoff =
            ((warpM + (lane & 15)) * ASTRIDE + ((lane >> 4) << 3)) * 2;
        const uint32_t boff =
            ((lane & 15) * BSTRIDE + warpN + ((lane >> 4) << 3)) * 2;

        uint32_t ah[2][4][4], al[2][4][4], bh[2][2][4], bl[2][2][4];

        auto ldsm_half = [&](int s, uint32_t sa, int ks) {
            const uint32_t aaddr = sa + aoff;
            const uint32_t baddr = sa + 2 * A_BYTES + boff;
#pragma unroll
            for (int mt = 0; mt < 4; mt++) {
                ldsm_x4(ah[s][mt], aaddr + (mt * 16 * ASTRIDE + ks) * 2);
                ldsm_x4(al[s][mt], aaddr + A_BYTES + (mt * 16 * ASTRIDE + ks) * 2);
            }
#pragma unroll
            for (int np = 0; np < 2; np++) {
                ldsm_x4_t(bh[s][np], baddr + (ks * BSTRIDE + np * 16) * 2);
                ldsm_x4_t(bl[s][np], baddr + B_BYTES + (ks * BSTRIDE + np * 16) * 2);
            }
        };
        auto mma_half = [&](int s) {
#pragma unroll
            for (int mt = 0; mt < 4; mt++)
#pragma unroll
                for (int nt = 0; nt < 4; nt++)
                    mma16816(acc[mt][nt], ah[s][mt], &bh[s][nt >> 1][(nt & 1) * 2]);
#pragma unroll
            for (int mt = 0; mt < 4; mt++)
#pragma unroll
                for (int nt = 0; nt < 4; nt++)
                    mma16816(acc[mt][nt], ah[s][mt], &bl[s][nt >> 1][(nt & 1) * 2]);
#pragma unroll
            for (int mt = 0; mt < 4; mt++)
#pragma unroll
                for (int nt = 0; nt < 4; nt++)
                    mma16816(acc[mt][nt], al[s][mt], &bh[s][nt >> 1][(nt & 1) * 2]);
        };

        // ---- prologue ----
        load_stage(0, itBase + 0);
        load_stage(1, itBase + 1);
        load_stage(2, itBase + 2);
        asm volatile("cp.async.wait_group %0;" :: "n"(2));
        __syncthreads();
        ldsm_half(0, sbase, 0);

        // ---- main loop ----
#pragma unroll 1
        for (int li = 0; li < NC; li++) {
            const uint32_t sa = sbase + (li & 3) * STAGE_BYTES;
            ldsm_half(1, sa, 16);
            mma_half(0);
            if (li + 1 < NC) {
                asm volatile("cp.async.wait_group %0;" :: "n"(1));
                __syncthreads();
                if (li + 3 < NC) load_stage((li + 3) & 3, itBase + li + 3);
                ldsm_half(0, sbase + ((li + 1) & 3) * STAGE_BYTES, 0);
            }
            mma_half(1);
        }
    }

    // ---- epilogue ----
    const int mrow0 = p0 + warpM + (lane >> 2);
    const int colb  = n0 + warpN + 2 * (lane & 3);
    if (SPLITK) {
        // raw partials (no bias/gelu/mask) to g_part plane zspl
        float* plane = g_part + (long)zspl * Mtot * CDIM;
#pragma unroll
        for (int mt = 0; mt < 4; mt++)
#pragma unroll
            for (int half = 0; half < 2; half++) {
                int row = mrow0 + mt * 16 + half * 8;
                if (row >= Mtot) continue;
                long base = (long)row * CDIM;
#pragma unroll
                for (int nt = 0; nt < 4; nt++) {
                    int col = colb + nt * 8;
                    *(float2*)(plane + base + col) =
                        make_float2(acc[mt][nt][half * 2], acc[mt][nt][half * 2 + 1]);
                }
            }
        return;
    }
#pragma unroll
    for (int mt = 0; mt < 4; mt++) {
#pragma unroll
        for (int half = 0; half < 2; half++) {
            int row = mrow0 + mt * 16 + half * 8;
            if (row >= Mtot) continue;
            int b = row / Pout;
            int p = row - b * Pout;
            int L = lengths[b];
            for (int t = 0; t < level; t++) L = (L - 1) / 2 + 1;
            int lenOut = DO_GELU ? L : ((L - 1) / 2 + 1);
            bool valid = (p < lenOut) && anyValid;
            long base = (long)row * CDIM;
#pragma unroll
            for (int nt = 0; nt < 4; nt++) {
                int col = colb + nt * 8;
                float z0 = 0.f, z1 = 0.f;
                if (valid) {
                    z0 = acc[mt][nt][half * 2 + 0] + __ldg(&bias[col]);
                    z1 = acc[mt][nt][half * 2 + 1] + __ldg(&bias[col + 1]);
                    if (DO_GELU) { z0 = gelu_exact(z0); z1 = gelu_exact(z1); }
                }
                __nv_bfloat162 h2, l2;
                split_bf16(z0, h2.x, l2.x);
                split_bf16(z1, h2.y, l2.y);
                if (DO_GELU) {
                    *(__nv_bfloat162*)(g_hhi + base + col) = h2;
                    *(__nv_bfloat162*)(g_hlo + base + col) = l2;
                } else {
                    float2 o2 = make_float2(z0, z1);
                    *(float2*)(outY + base + col) = o2;
                    *(__nv_bfloat162*)(g_xhi + base + col) = h2;
                    *(__nv_bfloat162*)(g_xlo + base + col) = l2;
                }
            }
        }
    }
}

// ---------------------------------------------------------------------------
extern "C" void kernel_launch(void* const* d_in, const int* in_sizes, int n_in,
                              void* d_out, int out_size) {
    const float* seq     = (const float*)d_in[0];
    const int*   lengths = (const int*)  d_in[1];
    const float* w1      = (const float*)d_in[2];
    const float* b1      = (const float*)d_in[3];
    const float* w2      = (const float*)d_in[4];
    const float* b2      = (const float*)d_in[5];
    float* out = (float*)d_out;

    cudaFuncSetAttribute(conv_mma<1, true, false>,
                         cudaFuncAttributeMaxDynamicSharedMemorySize, SMEM_BYTES);
    cudaFuncSetAttribute(conv_mma<2, false, false>,
                         cudaFuncAttributeMaxDynamicSharedMemorySize, SMEM_BYTES);
    cudaFuncSetAttribute(conv_mma<1, true, true>,
                         cudaFuncAttributeMaxDynamicSharedMemorySize, SMEM_BYTES);
    cudaFuncSetAttribute(conv_mma<2, false, true>,
                         cudaFuncAttributeMaxDynamicSharedMemorySize, SMEM_BYTES);

    prep_weights<<<256, 256>>>(w1, w2);
    prep_input<<<512, 256>>>(seq, lengths);
    mask_kernel<<<64, 256>>>(out, lengths);

    int P = 2048;
    long off = 0;
    for (int lvl = 0; lvl < NLEV; lvl++) {
        int Pout = (P - 1) / 2 + 1;
        int M1 = BZ * P;
        int gx1 = (M1 + BM - 1) / BM;
        if (M1 > SPLIT_MAX_M) {
            conv_mma<1, true, false><<<dim3(gx1, CDIM / BN), 256, SMEM_BYTES>>>(
                b1, nullptr, P, P, lengths, lvl);
        } else {
            conv_mma<1, true, true><<<dim3(gx1, CDIM / BN, NSPL), 256,
                                      SMEM_BYTES>>>(b1, nullptr, P, P, lengths,
                                                    lvl);
            long pairs = (long)M1 * (CDIM / 2);
            int blocks = (int)((pairs + 255) / 256);
            if (blocks > 2048) blocks = 2048;
            reduce_split<true><<<blocks, 256>>>(b1, nullptr, P, lengths, lvl, M1);
        }
        int M2 = BZ * Pout;
        int gx2 = (M2 + BM - 1) / BM;
        if (M2 > SPLIT_MAX_M) {
            conv_mma<2, false, false><<<dim3(gx2, CDIM / BN), 256, SMEM_BYTES>>>(
                b2, out + off, P, Pout, lengths, lvl);
        } else {
            conv_mma<2, false, true><<<dim3(gx2, CDIM / BN, NSPL), 256,
                                       SMEM_BYTES>>>(b2, nullptr, P, Pout,
                                                     lengths, lvl);
            long pairs = (long)M2 * (CDIM / 2);
            int blocks = (int)((pairs + 255) / 256);
            if (blocks > 2048) blocks = 2048;
            reduce_split<false><<<blocks, 256>>>(b2, out + off, Pout, lengths,
                                                 lvl, M2);
        }
        off += (long)BZ * Pout * CDIM + (long)BZ * Pout;
        P = Pout;
    }
}

// round 11
// speedup vs baseline: 1.7121x; 1.0253x over previous
#include <cuda_runtime.h>
#include <cuda_bf16.h>
#include <math.h>
#include <cstdint>

// ---------------------------------------------------------------------------
// TreeGetter: 11-level conv halving tree as implicit GEMM on mma.sync (bf16,
// hi/lo 3-product split). 128x128x32 block, 8 warps, 64x32 warp tile, 4-stage
// cp.async pipeline + fragment double-buffering. Full-masked M-tile skip.
// Split-K with per-level depth (3/6/12/24) keyed to grid occupancy; partials
// to fp32 workspace + reduce kernel. Last-chunk wait_group(0) hazard fix.
// ---------------------------------------------------------------------------

#define CDIM 768
#define CK   2304
#define NLEV 11
#define BZ   16
#define BM   128
#define BN   128
#define BKC  32
#define NCH  (CK / BKC)      // 72

#define ASTRIDE 40           // bf16 elems per A row (32 + 8 pad) = 80B
#define BSTRIDE 136          // bf16 elems per B row (128 + 8 pad) = 272B
#define A_BYTES (BM * ASTRIDE * 2)               // 10240
#define B_BYTES (BKC * BSTRIDE * 2)              // 8704
#define STAGE_BYTES (2 * A_BYTES + 2 * B_BYTES)  // 37888
#define SMEM_BYTES (4 * STAGE_BYTES)             // 151552

// ---------------- scratch (device globals; allocation-free rule) ------------
#define MAXE ((long)BZ * 2048 * CDIM)
__device__ __nv_bfloat16 g_xhi[MAXE], g_xlo[MAXE];   // conv1 input splits
__device__ __nv_bfloat16 g_hhi[MAXE], g_hlo[MAXE];   // conv2 input splits
__device__ __nv_bfloat16 g_w1hi[CK * CDIM], g_w1lo[CK * CDIM];
__device__ __nv_bfloat16 g_w2hi[CK * CDIM], g_w2lo[CK * CDIM];
// split-K partials: max planes*rows = 3*8192 = 24576 rows
__device__ float g_part[(long)24576 * CDIM];

__device__ __forceinline__ void split_bf16(float v, __nv_bfloat16& hi,
                                           __nv_bfloat16& lo) {
    hi = __float2bfloat16(v);
    lo = __float2bfloat16(v - __bfloat162float(hi));
}

__device__ __forceinline__ uint32_t smem_u32(const void* p) {
    uint32_t a;
    asm("{ .reg .u64 t; cvta.to.shared.u64 t, %1; cvt.u32.u64 %0, t; }"
        : "=r"(a) : "l"(p));
    return a;
}
__device__ __forceinline__ void cp_async16(uint32_t dst, const void* src,
                                           bool pred) {
    int sz = pred ? 16 : 0;
    asm volatile("cp.async.cg.shared.global [%0], [%1], 16, %2;"
                 :: "r"(dst), "l"(src), "r"(sz));
}
__device__ __forceinline__ void cp_commit() {
    asm volatile("cp.async.commit_group;");
}
__device__ __forceinline__ void ldsm_x4(uint32_t* r, uint32_t a) {
    asm volatile("ldmatrix.sync.aligned.m8n8.x4.shared.b16 {%0,%1,%2,%3}, [%4];"
                 : "=r"(r[0]), "=r"(r[1]), "=r"(r[2]), "=r"(r[3]) : "r"(a));
}
__device__ __forceinline__ void ldsm_x4_t(uint32_t* r, uint32_t a) {
    asm volatile("ldmatrix.sync.aligned.m8n8.x4.trans.shared.b16 {%0,%1,%2,%3}, [%4];"
                 : "=r"(r[0]), "=r"(r[1]), "=r"(r[2]), "=r"(r[3]) : "r"(a));
}
__device__ __forceinline__ void mma16816(float* d, const uint32_t* a,
                                         const uint32_t* b) {
    asm("mma.sync.aligned.m16n8k16.row.col.f32.bf16.bf16.f32 "
        "{%0,%1,%2,%3}, {%4,%5,%6,%7}, {%8,%9}, {%0,%1,%2,%3};"
        : "+f"(d[0]), "+f"(d[1]), "+f"(d[2]), "+f"(d[3])
        : "r"(a[0]), "r"(a[1]), "r"(a[2]), "r"(a[3]), "r"(b[0]), "r"(b[1]));
}
__device__ __forceinline__ float gelu_exact(float z) {
    return 0.5f * z * (1.f + erff(z * 0.70710678118654752f));
}

// ---------------------------------------------------------------------------
__global__ void prep_weights(const float* __restrict__ w1,
                             const float* __restrict__ w2) {
    int total = CK * CDIM;
    for (int j = blockIdx.x * blockDim.x + threadIdx.x; j < total;
         j += gridDim.x * blockDim.x) {
        int o  = j % CDIM;
        int kg = j / CDIM;
        int d  = kg / CDIM;
        int i  = kg - d * CDIM;
        long src = (long)o * CK + i * 3 + d;   // w[o][i][d]
        split_bf16(w1[src], g_w1hi[j], g_w1lo[j]);
        split_bf16(w2[src], g_w2hi[j], g_w2lo[j]);
    }
}

__global__ void prep_input(const float* __restrict__ seq,
                           const int* __restrict__ lengths) {
    long total = MAXE;
    for (long j = blockIdx.x * (long)blockDim.x + threadIdx.x; j < total;
         j += gridDim.x * (long)blockDim.x) {
        long bp = j / CDIM;
        int p = (int)(bp % 2048);
        int b = (int)(bp / 2048);
        float v = (p < lengths[b]) ? seq[j] : 0.f;
        split_bf16(v, g_xhi[j], g_xlo[j]);
    }
}

__global__ void mask_kernel(float* __restrict__ out,
                            const int* __restrict__ lengths) {
    int idx    = blockIdx.x * blockDim.x + threadIdx.x;
    int stride = gridDim.x * blockDim.x;
    long off = 0;
    int P = 2048;
    for (int lvl = 0; lvl < NLEV; lvl++) {
        int Pout = (P - 1) / 2 + 1;
        long maskOff = off + (long)BZ * Pout * CDIM;
        int n = BZ * Pout;
        for (int i = idx; i < n; i += stride) {
            int b = i / Pout, p = i % Pout;
            int L = lengths[b];
            for (int t = 0; t <= lvl; t++) L = (L - 1) / 2 + 1;
            out[maskOff + i] = (p < L) ? 1.f : 0.f;
        }
        off = maskOff + n;
        P = Pout;
    }
}

// ---------------------------------------------------------------------------
// reduce for split-K: sum nspl planes + bias (+gelu) + mask, write bf16 splits.
template <bool DO_GELU>
__global__ void reduce_split(const float* __restrict__ bias,
                             float* __restrict__ outY, int Pout,
                             const int* __restrict__ lengths, int level,
                             int Mtot, int nspl) {
    long total = (long)Mtot * (CDIM / 2);
    long plane = (long)Mtot * CDIM;
    for (long i = blockIdx.x * (long)blockDim.x + threadIdx.x; i < total;
         i += gridDim.x * (long)blockDim.x) {
        int row = (int)(i / (CDIM / 2));
        int col = (int)(i % (CDIM / 2)) * 2;
        int b = row / Pout, p = row - b * Pout;
        int L = lengths[b];
        for (int t = 0; t < level; t++) L = (L - 1) / 2 + 1;
        int lenOut = DO_GELU ? L : ((L - 1) / 2 + 1);
        float z0 = 0.f, z1 = 0.f;
        if (p < lenOut) {
            long off = (long)row * CDIM + col;
            for (int s = 0; s < nspl; s++) {
                float2 v = *(const float2*)(g_part + (long)s * plane + off);
                z0 += v.x;
                z1 += v.y;
            }
            z0 += __ldg(&bias[col]);
            z1 += __ldg(&bias[col + 1]);
            if (DO_GELU) { z0 = gelu_exact(z0); z1 = gelu_exact(z1); }
        }
        __nv_bfloat162 h2, l2;
        split_bf16(z0, h2.x, l2.x);
        split_bf16(z1, h2.y, l2.y);
        long base = (long)row * CDIM + col;
        if (DO_GELU) {
            *(__nv_bfloat162*)(g_hhi + base) = h2;
            *(__nv_bfloat162*)(g_hlo + base) = l2;
        } else {
            *(float2*)(outY + base) = make_float2(z0, z1);
            *(__nv_bfloat162*)(g_xhi + base) = h2;
            *(__nv_bfloat162*)(g_xlo + base) = l2;
        }
    }
}

// ---------------------------------------------------------------------------
// Implicit-GEMM conv on mma.sync with fragment double-buffering.
// SPLITK: blockIdx.z = split index, NCH/nspl chunks, raw partials to g_part.
template <int STRIDE, bool DO_GELU, bool SPLITK>
__global__ void __launch_bounds__(256, 1)
conv_mma(const float* __restrict__ bias, float* __restrict__ outY,
         int Pin, int Pout, const int* __restrict__ lengths, int level,
         int nspl) {
    extern __shared__ char smem[];
    const uint32_t sbase = smem_u32(smem);
    const int tid   = threadIdx.x;
    const int lane  = tid & 31;
    const int wid   = tid >> 5;
    const int warpM = (wid & 1) * 64;
    const int warpN = (wid >> 1) * 32;
    const int p0    = blockIdx.x * BM;
    const int n0    = blockIdx.y * BN;
    const int Mtot  = BZ * Pout;
    const int NC     = SPLITK ? (NCH / nspl) : NCH;
    const int itBase = SPLITK ? (int)blockIdx.z * NC : 0;

    const __nv_bfloat16* Xhi = DO_GELU ? g_xhi : g_hhi;
    const __nv_bfloat16* Xlo = DO_GELU ? g_xlo : g_hlo;
    const __nv_bfloat16* Whi = DO_GELU ? g_w1hi : g_w2hi;
    const __nv_bfloat16* Wlo = DO_GELU ? g_w1lo : g_w2lo;

    float acc[4][4][4];
#pragma unroll
    for (int a = 0; a < 4; a++)
#pragma unroll
        for (int b = 0; b < 4; b++)
#pragma unroll
            for (int c = 0; c < 4; c++) acc[a][b][c] = 0.f;

    // ---- full-masked tile skip ----
    bool anyValid = false;
    {
        int bA = p0 / Pout;
        int bB = (p0 + BM - 1) / Pout;
        if (bB >= BZ) bB = BZ - 1;
        for (int b = bA; b <= bB; b++) {
            int L = lengths[b];
            for (int t = 0; t < level; t++) L = (L - 1) / 2 + 1;
            int lenOut = DO_GELU ? L : ((L - 1) / 2 + 1);
            int pstart = p0 > b * Pout ? p0 - b * Pout : 0;
            if (pstart < lenOut) { anyValid = true; break; }
        }
    }

    if (anyValid) {
        // ---- per-thread load geometry ----
        int aPosB[2]; long aRowBase[2]; bool aOk[2];
        const int akc = tid & 3;
#pragma unroll
        for (int i = 0; i < 2; i++) {
            int r = (tid + i * 256) >> 2;
            int grow = p0 + r;
            bool ok = grow < Mtot;
            int b = ok ? grow / Pout : 0;
            int p = grow - b * Pout;
            aOk[i] = ok;
            aPosB[i] = p * STRIDE - 1;
            aRowBase[i] = (long)b * Pin;
        }
        const int bkrow0 = tid >> 4;
        const int bnc = tid & 15;

        auto load_stage = [&](int slot, int it) {
            const uint32_t sa = sbase + slot * STAGE_BYTES;
            const int kk = it * BKC;
            const int d  = (kk >= 1536) ? 2 : (kk >= 768 ? 1 : 0);
            const int c0 = kk - d * CDIM;
#pragma unroll
            for (int i = 0; i < 2; i++) {
                int id  = tid + i * 256;
                int row = id >> 2;
                int pos = aPosB[i] + d;
                bool v = aOk[i] && pos >= 0 && pos < Pin;
                long g = v ? ((aRowBase[i] + pos) * CDIM + c0 + akc * 8) : 0;
                uint32_t dst = sa + (row * ASTRIDE + akc * 8) * 2;
                cp_async16(dst, Xhi + g, v);
                cp_async16(dst + A_BYTES, Xlo + g, v);
            }
#pragma unroll
            for (int i = 0; i < 2; i++) {
                int krow = bkrow0 + i * 16;
                long g = (long)(kk + krow) * CDIM + n0 + bnc * 8;
                uint32_t dst = sa + 2 * A_BYTES + (krow * BSTRIDE + bnc * 8) * 2;
                cp_async16(dst, Whi + g, true);
                cp_async16(dst + B_BYTES, Wlo + g, true);
            }
            cp_commit();
        };

        const uint32_t aoff =
            ((warpM + (lane & 15)) * ASTRIDE + ((lane >> 4) << 3)) * 2;
        const uint32_t boff =
            ((lane & 15) * BSTRIDE + warpN + ((lane >> 4) << 3)) * 2;

        uint32_t ah[2][4][4], al[2][4][4], bh[2][2][4], bl[2][2][4];

        auto ldsm_half = [&](int s, uint32_t sa, int ks) {
            const uint32_t aaddr = sa + aoff;
            const uint32_t baddr = sa + 2 * A_BYTES + boff;
#pragma unroll
            for (int mt = 0; mt < 4; mt++) {
                ldsm_x4(ah[s][mt], aaddr + (mt * 16 * ASTRIDE + ks) * 2);
                ldsm_x4(al[s][mt], aaddr + A_BYTES + (mt * 16 * ASTRIDE + ks) * 2);
            }
#pragma unroll
            for (int np = 0; np < 2; np++) {
                ldsm_x4_t(bh[s][np], baddr + (ks * BSTRIDE + np * 16) * 2);
                ldsm_x4_t(bl[s][np], baddr + B_BYTES + (ks * BSTRIDE + np * 16) * 2);
            }
        };
        auto mma_half = [&](int s) {
#pragma unroll
            for (int mt = 0; mt < 4; mt++)
#pragma unroll
                for (int nt = 0; nt < 4; nt++)
                    mma16816(acc[mt][nt], ah[s][mt], &bh[s][nt >> 1][(nt & 1) * 2]);
#pragma unroll
            for (int mt = 0; mt < 4; mt++)
#pragma unroll
                for (int nt = 0; nt < 4; nt++)
                    mma16816(acc[mt][nt], ah[s][mt], &bl[s][nt >> 1][(nt & 1) * 2]);
#pragma unroll
            for (int mt = 0; mt < 4; mt++)
#pragma unroll
                for (int nt = 0; nt < 4; nt++)
                    mma16816(acc[mt][nt], al[s][mt], &bh[s][nt >> 1][(nt & 1) * 2]);
        };

        // ---- prologue (NC >= 3 always) ----
        load_stage(0, itBase + 0);
        load_stage(1, itBase + 1);
        load_stage(2, itBase + 2);
        asm volatile("cp.async.wait_group %0;" :: "n"(2));
        __syncthreads();
        ldsm_half(0, sbase, 0);

        // ---- main loop ----
#pragma unroll 1
        for (int li = 0; li < NC; li++) {
            const uint32_t sa = sbase + (li & 3) * STAGE_BYTES;
            ldsm_half(1, sa, 16);
            mma_half(0);
            if (li + 1 < NC) {
                // chunk li+1 must be complete. It is the NEWEST group when
                // li+2 == NC, so wait for ALL groups in that case.
                if (li + 2 < NC) {
                    asm volatile("cp.async.wait_group %0;" :: "n"(1));
                } else {
                    asm volatile("cp.async.wait_group %0;" :: "n"(0));
                }
                __syncthreads();
                if (li + 3 < NC) load_stage((li + 3) & 3, itBase + li + 3);
                ldsm_half(0, sbase + ((li + 1) & 3) * STAGE_BYTES, 0);
            }
            mma_half(1);
        }
    }

    // ---- epilogue ----
    const int mrow0 = p0 + warpM + (lane >> 2);
    const int colb  = n0 + warpN + 2 * (lane & 3);
    if (SPLITK) {
        if (!anyValid) return;   // reduce masks these rows anyway
        float* plane = g_part + (long)blockIdx.z * Mtot * CDIM;
#pragma unroll
        for (int mt = 0; mt < 4; mt++)
#pragma unroll
            for (int half = 0; half < 2; half++) {
                int row = mrow0 + mt * 16 + half * 8;
                if (row >= Mtot) continue;
                long base = (long)row * CDIM;
#pragma unroll
                for (int nt = 0; nt < 4; nt++) {
                    int col = colb + nt * 8;
                    *(float2*)(plane + base + col) =
                        make_float2(acc[mt][nt][half * 2], acc[mt][nt][half * 2 + 1]);
                }
            }
        return;
    }
#pragma unroll
    for (int mt = 0; mt < 4; mt++) {
#pragma unroll
        for (int half = 0; half < 2; half++) {
            int row = mrow0 + mt * 16 + half * 8;
            if (row >= Mtot) continue;
            int b = row / Pout;
            int p = row - b * Pout;
            int L = lengths[b];
            for (int t = 0; t < level; t++) L = (L - 1) / 2 + 1;
            int lenOut = DO_GELU ? L : ((L - 1) / 2 + 1);
            bool valid = (p < lenOut) && anyValid;
            long base = (long)row * CDIM;
#pragma unroll
            for (int nt = 0; nt < 4; nt++) {
                int col = colb + nt * 8;
                float z0 = 0.f, z1 = 0.f;
                if (valid) {
                    z0 = acc[mt][nt][half * 2 + 0] + __ldg(&bias[col]);
                    z1 = acc[mt][nt][half * 2 + 1] + __ldg(&bias[col + 1]);
                    if (DO_GELU) { z0 = gelu_exact(z0); z1 = gelu_exact(z1); }
                }
                __nv_bfloat162 h2, l2;
                split_bf16(z0, h2.x, l2.x);
                split_bf16(z1, h2.y, l2.y);
                if (DO_GELU) {
                    *(__nv_bfloat162*)(g_hhi + base + col) = h2;
                    *(__nv_bfloat162*)(g_hlo + base + col) = l2;
                } else {
                    float2 o2 = make_float2(z0, z1);
                    *(float2*)(outY + base + col) = o2;
                    *(__nv_bfloat162*)(g_xhi + base + col) = h2;
                    *(__nv_bfloat16*)(g_xlo + base + col) = l2.x;
                    *(__nv_bfloat16*)(g_xlo + base + col + 1) = l2.y;
                }
            }
        }
    }
}

// ---------------------------------------------------------------------------
static inline int pick_nspl(int M) {
    if (M > 8192) return 0;     // no split: grid already >= ~3 waves
    if (M >= 1024) return 3;    // path 72 -> 24
    if (M == 512) return 6;     // path -> 12 (144 CTAs, 1 wave)
    if (M == 256) return 12;    // path -> 6
    return 24;                  // M <= 128: path -> 3
}

extern "C" void kernel_launch(void* const* d_in, const int* in_sizes, int n_in,
                              void* d_out, int out_size) {
    const float* seq     = (const float*)d_in[0];
    const int*   lengths = (const int*)  d_in[1];
    const float* w1      = (const float*)d_in[2];
    const float* b1      = (const float*)d_in[3];
    const float* w2      = (const float*)d_in[4];
    const float* b2      = (const float*)d_in[5];
    float* out = (float*)d_out;

    cudaFuncSetAttribute(conv_mma<1, true, false>,
                         cudaFuncAttributeMaxDynamicSharedMemorySize, SMEM_BYTES);
    cudaFuncSetAttribute(conv_mma<2, false, false>,
                         cudaFuncAttributeMaxDynamicSharedMemorySize, SMEM_BYTES);
    cudaFuncSetAttribute(conv_mma<1, true, true>,
                         cudaFuncAttributeMaxDynamicSharedMemorySize, SMEM_BYTES);
    cudaFuncSetAttribute(conv_mma<2, false, true>,
                         cudaFuncAttributeMaxDynamicSharedMemorySize, SMEM_BYTES);

    prep_weights<<<256, 256>>>(w1, w2);
    prep_input<<<512, 256>>>(seq, lengths);
    mask_kernel<<<64, 256>>>(out, lengths);

    int P = 2048;
    long off = 0;
    for (int lvl = 0; lvl < NLEV; lvl++) {
        int Pout = (P - 1) / 2 + 1;
        // ---- conv1 ----
        int M1 = BZ * P;
        int gx1 = (M1 + BM - 1) / BM;
        int ns1 = pick_nspl(M1);
        if (ns1 == 0) {
            conv_mma<1, true, false><<<dim3(gx1, CDIM / BN), 256, SMEM_BYTES>>>(
                b1, nullptr, P, P, lengths, lvl, 0);
        } else {
            conv_mma<1, true, true><<<dim3(gx1, CDIM / BN, ns1), 256,
                                      SMEM_BYTES>>>(b1, nullptr, P, P, lengths,
                                                    lvl, ns1);
            long pairs = (long)M1 * (CDIM / 2);
            int blocks = (int)((pairs + 255) / 256);
            if (blocks > 2048) blocks = 2048;
            reduce_split<true><<<blocks, 256>>>(b1, nullptr, P, lengths, lvl,
                                                M1, ns1);
        }
        // ---- conv2 ----
        int M2 = BZ * Pout;
        int gx2 = (M2 + BM - 1) / BM;
        int ns2 = pick_nspl(M2);
        if (ns2 == 0) {
            conv_mma<2, false, false><<<dim3(gx2, CDIM / BN), 256, SMEM_BYTES>>>(
                b2, out + off, P, Pout, lengths, lvl, 0);
        } else {
            conv_mma<2, false, true><<<dim3(gx2, CDIM / BN, ns2), 256,
                                       SMEM_BYTES>>>(b2, nullptr, P, Pout,
                                                     lengths, lvl, ns2);
            long pairs = (long)M2 * (CDIM / 2);
            int blocks = (int)((pairs + 255) / 256);
            if (blocks > 2048) blocks = 2048;
            reduce_split<false><<<blocks, 256>>>(b2, out + off, Pout, lengths,
                                                 lvl, M2, ns2);
        }
        off += (long)BZ * Pout * CDIM + (long)BZ * Pout;
        P = Pout;
    }
}

// round 12
// speedup vs baseline: 2.1032x; 1.2284x over previous
#include <cuda_runtime.h>
#include <cuda_bf16.h>
#include <math.h>
#include <cstdint>

// ---------------------------------------------------------------------------
// TreeGetter: 11-level conv halving tree as implicit GEMM on mma.sync (bf16,
// hi/lo 3-product split). NEW geometry: 128-thread CTA (4 warps, 2Mx2N of
// 64x32 warp tiles) on a 128x64 block tile, 2-stage cp.async buffer ->
// 3 CTAs/SM co-residency (independent barrier phases overlap LSU vs tensor).
// Split-K depths retuned for 444-CTA concurrency. Masked-tile skip kept.
// ---------------------------------------------------------------------------

#define CDIM 768
#define CK   2304
#define NLEV 11
#define BZ   16
#define BM   128
#define BN   64
#define BKC  32
#define NCH  (CK / BKC)      // 72
#define THREADS 128

#define ASTRIDE 40           // bf16 elems per A row (32 + 8 pad) = 80B
#define BSTRIDE 72           // bf16 elems per B row (64 + 8 pad) = 144B
#define A_BYTES (BM * ASTRIDE * 2)               // 10240
#define B_BYTES (BKC * BSTRIDE * 2)              // 4608
#define STAGE_BYTES (2 * A_BYTES + 2 * B_BYTES)  // 29696
#define SMEM_BYTES (2 * STAGE_BYTES)             // 59392

// ---------------- scratch (device globals; allocation-free rule) ------------
#define MAXE ((long)BZ * 2048 * CDIM)
__device__ __nv_bfloat16 g_xhi[MAXE], g_xlo[MAXE];   // conv1 input splits
__device__ __nv_bfloat16 g_hhi[MAXE], g_hlo[MAXE];   // conv2 input splits
__device__ __nv_bfloat16 g_w1hi[CK * CDIM], g_w1lo[CK * CDIM];
__device__ __nv_bfloat16 g_w2hi[CK * CDIM], g_w2lo[CK * CDIM];
__device__ float g_part[(long)24576 * CDIM];         // split-K partials

__device__ __forceinline__ void split_bf16(float v, __nv_bfloat16& hi,
                                           __nv_bfloat16& lo) {
    hi = __float2bfloat16(v);
    lo = __float2bfloat16(v - __bfloat162float(hi));
}

__device__ __forceinline__ uint32_t smem_u32(const void* p) {
    uint32_t a;
    asm("{ .reg .u64 t; cvta.to.shared.u64 t, %1; cvt.u32.u64 %0, t; }"
        : "=r"(a) : "l"(p));
    return a;
}
__device__ __forceinline__ void cp_async16(uint32_t dst, const void* src,
                                           bool pred) {
    int sz = pred ? 16 : 0;
    asm volatile("cp.async.cg.shared.global [%0], [%1], 16, %2;"
                 :: "r"(dst), "l"(src), "r"(sz));
}
__device__ __forceinline__ void cp_commit() {
    asm volatile("cp.async.commit_group;");
}
__device__ __forceinline__ void ldsm_x4(uint32_t* r, uint32_t a) {
    asm volatile("ldmatrix.sync.aligned.m8n8.x4.shared.b16 {%0,%1,%2,%3}, [%4];"
                 : "=r"(r[0]), "=r"(r[1]), "=r"(r[2]), "=r"(r[3]) : "r"(a));
}
__device__ __forceinline__ void ldsm_x4_t(uint32_t* r, uint32_t a) {
    asm volatile("ldmatrix.sync.aligned.m8n8.x4.trans.shared.b16 {%0,%1,%2,%3}, [%4];"
                 : "=r"(r[0]), "=r"(r[1]), "=r"(r[2]), "=r"(r[3]) : "r"(a));
}
__device__ __forceinline__ void mma16816(float* d, const uint32_t* a,
                                         const uint32_t* b) {
    asm("mma.sync.aligned.m16n8k16.row.col.f32.bf16.bf16.f32 "
        "{%0,%1,%2,%3}, {%4,%5,%6,%7}, {%8,%9}, {%0,%1,%2,%3};"
        : "+f"(d[0]), "+f"(d[1]), "+f"(d[2]), "+f"(d[3])
        : "r"(a[0]), "r"(a[1]), "r"(a[2]), "r"(a[3]), "r"(b[0]), "r"(b[1]));
}
__device__ __forceinline__ float gelu_exact(float z) {
    return 0.5f * z * (1.f + erff(z * 0.70710678118654752f));
}

// ---------------------------------------------------------------------------
__global__ void prep_weights(const float* __restrict__ w1,
                             const float* __restrict__ w2) {
    int total = CK * CDIM;
    for (int j = blockIdx.x * blockDim.x + threadIdx.x; j < total;
         j += gridDim.x * blockDim.x) {
        int o  = j % CDIM;
        int kg = j / CDIM;
        int d  = kg / CDIM;
        int i  = kg - d * CDIM;
        long src = (long)o * CK + i * 3 + d;   // w[o][i][d]
        split_bf16(w1[src], g_w1hi[j], g_w1lo[j]);
        split_bf16(w2[src], g_w2hi[j], g_w2lo[j]);
    }
}

__global__ void prep_input(const float* __restrict__ seq,
                           const int* __restrict__ lengths) {
    long total = MAXE;
    for (long j = blockIdx.x * (long)blockDim.x + threadIdx.x; j < total;
         j += gridDim.x * (long)blockDim.x) {
        long bp = j / CDIM;
        int p = (int)(bp % 2048);
        int b = (int)(bp / 2048);
        float v = (p < lengths[b]) ? seq[j] : 0.f;
        split_bf16(v, g_xhi[j], g_xlo[j]);
    }
}

__global__ void mask_kernel(float* __restrict__ out,
                            const int* __restrict__ lengths) {
    int idx    = blockIdx.x * blockDim.x + threadIdx.x;
    int stride = gridDim.x * blockDim.x;
    long off = 0;
    int P = 2048;
    for (int lvl = 0; lvl < NLEV; lvl++) {
        int Pout = (P - 1) / 2 + 1;
        long maskOff = off + (long)BZ * Pout * CDIM;
        int n = BZ * Pout;
        for (int i = idx; i < n; i += stride) {
            int b = i / Pout, p = i % Pout;
            int L = lengths[b];
            for (int t = 0; t <= lvl; t++) L = (L - 1) / 2 + 1;
            out[maskOff + i] = (p < L) ? 1.f : 0.f;
        }
        off = maskOff + n;
        P = Pout;
    }
}

// ---------------------------------------------------------------------------
// reduce for split-K: sum nspl planes + bias (+gelu) + mask, write bf16 splits.
template <bool DO_GELU>
__global__ void reduce_split(const float* __restrict__ bias,
                             float* __restrict__ outY, int Pout,
                             const int* __restrict__ lengths, int level,
                             int Mtot, int nspl) {
    long total = (long)Mtot * (CDIM / 2);
    long plane = (long)Mtot * CDIM;
    for (long i = blockIdx.x * (long)blockDim.x + threadIdx.x; i < total;
         i += gridDim.x * (long)blockDim.x) {
        int row = (int)(i / (CDIM / 2));
        int col = (int)(i % (CDIM / 2)) * 2;
        int b = row / Pout, p = row - b * Pout;
        int L = lengths[b];
        for (int t = 0; t < level; t++) L = (L - 1) / 2 + 1;
        int lenOut = DO_GELU ? L : ((L - 1) / 2 + 1);
        float z0 = 0.f, z1 = 0.f;
        if (p < lenOut) {
            long off = (long)row * CDIM + col;
            for (int s = 0; s < nspl; s++) {
                float2 v = *(const float2*)(g_part + (long)s * plane + off);
                z0 += v.x;
                z1 += v.y;
            }
            z0 += __ldg(&bias[col]);
            z1 += __ldg(&bias[col + 1]);
            if (DO_GELU) { z0 = gelu_exact(z0); z1 = gelu_exact(z1); }
        }
        __nv_bfloat162 h2, l2;
        split_bf16(z0, h2.x, l2.x);
        split_bf16(z1, h2.y, l2.y);
        long base = (long)row * CDIM + col;
        if (DO_GELU) {
            *(__nv_bfloat162*)(g_hhi + base) = h2;
            *(__nv_bfloat162*)(g_hlo + base) = l2;
        } else {
            *(float2*)(outY + base) = make_float2(z0, z1);
            *(__nv_bfloat162*)(g_xhi + base) = h2;
            *(__nv_bfloat162*)(g_xlo + base) = l2;
        }
    }
}

// ---------------------------------------------------------------------------
// Implicit-GEMM conv on mma.sync.  128 threads = 4 warps (2M x 2N), warp
// tile 64x32, block 128x64x32. 2-stage buffer; 3 CTAs co-resident per SM.
template <int STRIDE, bool DO_GELU, bool SPLITK>
__global__ void __launch_bounds__(THREADS, 3)
conv_mma(const float* __restrict__ bias, float* __restrict__ outY,
         int Pin, int Pout, const int* __restrict__ lengths, int level,
         int nspl) {
    extern __shared__ char smem[];
    const uint32_t sbase = smem_u32(smem);
    const int tid   = threadIdx.x;
    const int lane  = tid & 31;
    const int wid   = tid >> 5;
    const int warpM = (wid & 1) * 64;
    const int warpN = (wid >> 1) * 32;
    const int p0    = blockIdx.x * BM;
    const int n0    = blockIdx.y * BN;
    const int Mtot  = BZ * Pout;
    const int NC     = SPLITK ? (NCH / nspl) : NCH;
    const int itBase = SPLITK ? (int)blockIdx.z * NC : 0;

    const __nv_bfloat16* Xhi = DO_GELU ? g_xhi : g_hhi;
    const __nv_bfloat16* Xlo = DO_GELU ? g_xlo : g_hlo;
    const __nv_bfloat16* Whi = DO_GELU ? g_w1hi : g_w2hi;
    const __nv_bfloat16* Wlo = DO_GELU ? g_w1lo : g_w2lo;

    float acc[4][4][4];
#pragma unroll
    for (int a = 0; a < 4; a++)
#pragma unroll
        for (int b = 0; b < 4; b++)
#pragma unroll
            for (int c = 0; c < 4; c++) acc[a][b][c] = 0.f;

    // ---- full-masked tile skip ----
    bool anyValid = false;
    {
        int bA = p0 / Pout;
        int bB = (p0 + BM - 1) / Pout;
        if (bB >= BZ) bB = BZ - 1;
        for (int b = bA; b <= bB; b++) {
            int L = lengths[b];
            for (int t = 0; t < level; t++) L = (L - 1) / 2 + 1;
            int lenOut = DO_GELU ? L : ((L - 1) / 2 + 1);
            int pstart = p0 > b * Pout ? p0 - b * Pout : 0;
            if (pstart < lenOut) { anyValid = true; break; }
        }
    }

    if (anyValid) {
        // ---- per-thread load geometry ----
        // A: 512 16B-chunks/plane: id = tid + i*128; row = id>>2, kc = id&3
        int aPosB[4]; long aRowBase[4]; bool aOk[4];
        const int akc = tid & 3;
#pragma unroll
        for (int i = 0; i < 4; i++) {
            int r = (tid + i * THREADS) >> 2;
            int grow = p0 + r;
            bool ok = grow < Mtot;
            int b = ok ? grow / Pout : 0;
            int p = grow - b * Pout;
            aOk[i] = ok;
            aPosB[i] = p * STRIDE - 1;
            aRowBase[i] = (long)b * Pin;
        }
        // B: 256 chunks/plane: id = tid + i*128; krow = id>>3, nc = id&7
        const int bnc = tid & 7;

        auto load_stage = [&](int slot, int it) {
            const uint32_t sa = sbase + slot * STAGE_BYTES;
            const int kk = it * BKC;
            const int d  = (kk >= 1536) ? 2 : (kk >= 768 ? 1 : 0);
            const int c0 = kk - d * CDIM;
#pragma unroll
            for (int i = 0; i < 4; i++) {
                int row = (tid + i * THREADS) >> 2;
                int pos = aPosB[i] + d;
                bool v = aOk[i] && pos >= 0 && pos < Pin;
                long g = v ? ((aRowBase[i] + pos) * CDIM + c0 + akc * 8) : 0;
                uint32_t dst = sa + (row * ASTRIDE + akc * 8) * 2;
                cp_async16(dst, Xhi + g, v);
                cp_async16(dst + A_BYTES, Xlo + g, v);
            }
#pragma unroll
            for (int i = 0; i < 2; i++) {
                int krow = (tid + i * THREADS) >> 3;
                long g = (long)(kk + krow) * CDIM + n0 + bnc * 8;
                uint32_t dst = sa + 2 * A_BYTES + (krow * BSTRIDE + bnc * 8) * 2;
                cp_async16(dst, Whi + g, true);
                cp_async16(dst + B_BYTES, Wlo + g, true);
            }
            cp_commit();
        };

        const uint32_t aoff =
            ((warpM + (lane & 15)) * ASTRIDE + ((lane >> 4) << 3)) * 2;
        const uint32_t boff =
            ((lane & 15) * BSTRIDE + warpN + ((lane >> 4) << 3)) * 2;

        uint32_t ah[4][4], al[4][4], bh[2][4], bl[2][4];

        auto ldsm_half = [&](uint32_t sa, int ks) {
            const uint32_t aaddr = sa + aoff;
            const uint32_t baddr = sa + 2 * A_BYTES + boff;
#pragma unroll
            for (int mt = 0; mt < 4; mt++) {
                ldsm_x4(ah[mt], aaddr + (mt * 16 * ASTRIDE + ks) * 2);
                ldsm_x4(al[mt], aaddr + A_BYTES + (mt * 16 * ASTRIDE + ks) * 2);
            }
#pragma unroll
            for (int np = 0; np < 2; np++) {
                ldsm_x4_t(bh[np], baddr + (ks * BSTRIDE + np * 16) * 2);
                ldsm_x4_t(bl[np], baddr + B_BYTES + (ks * BSTRIDE + np * 16) * 2);
            }
        };
        auto mma_half = [&]() {
#pragma unroll
            for (int mt = 0; mt < 4; mt++)
#pragma unroll
                for (int nt = 0; nt < 4; nt++)
                    mma16816(acc[mt][nt], ah[mt], &bh[nt >> 1][(nt & 1) * 2]);
#pragma unroll
            for (int mt = 0; mt < 4; mt++)
#pragma unroll
                for (int nt = 0; nt < 4; nt++)
                    mma16816(acc[mt][nt], ah[mt], &bl[nt >> 1][(nt & 1) * 2]);
#pragma unroll
            for (int mt = 0; mt < 4; mt++)
#pragma unroll
                for (int nt = 0; nt < 4; nt++)
                    mma16816(acc[mt][nt], al[mt], &bh[nt >> 1][(nt & 1) * 2]);
        };

        // ---- prologue (NC >= 2 always) ----
        load_stage(0, itBase + 0);
        load_stage(1, itBase + 1);

        // ---- main loop: 2-stage, single fragment set, prefetch into the
        //      slot just consumed (after all warps' ldsm: 2nd sync) ----
#pragma unroll 1
        for (int li = 0; li < NC; li++) {
            asm volatile("cp.async.wait_group %0;" :: "n"(1));
            __syncthreads();
            const uint32_t sa = sbase + (li & 1) * STAGE_BYTES;
            ldsm_half(sa, 0);
            mma_half();
            ldsm_half(sa, 16);
            __syncthreads();     // slot fully read by all warps
            if (li + 2 < NC) load_stage(li & 1, itBase + li + 2);
            else cp_commit();    // keep group count uniform
            mma_half();
        }
    }

    // ---- epilogue ----
    const int mrow0 = p0 + warpM + (lane >> 2);
    const int colb  = n0 + warpN + 2 * (lane & 3);
    if (SPLITK) {
        if (!anyValid) return;   // reduce masks these rows anyway
        float* plane = g_part + (long)blockIdx.z * Mtot * CDIM;
#pragma unroll
        for (int mt = 0; mt < 4; mt++)
#pragma unroll
            for (int half = 0; half < 2; half++) {
                int row = mrow0 + mt * 16 + half * 8;
                if (row >= Mtot) continue;
                long base = (long)row * CDIM;
#pragma unroll
                for (int nt = 0; nt < 4; nt++) {
                    int col = colb + nt * 8;
                    *(float2*)(plane + base + col) =
                        make_float2(acc[mt][nt][half * 2], acc[mt][nt][half * 2 + 1]);
                }
            }
        return;
    }
#pragma unroll
    for (int mt = 0; mt < 4; mt++) {
#pragma unroll
        for (int half = 0; half < 2; half++) {
            int row = mrow0 + mt * 16 + half * 8;
            if (row >= Mtot) continue;
            int b = row / Pout;
            int p = row - b * Pout;
            int L = lengths[b];
            for (int t = 0; t < level; t++) L = (L - 1) / 2 + 1;
            int lenOut = DO_GELU ? L : ((L - 1) / 2 + 1);
            bool valid = (p < lenOut) && anyValid;
            long base = (long)row * CDIM;
#pragma unroll
            for (int nt = 0; nt < 4; nt++) {
                int col = colb + nt * 8;
                float z0 = 0.f, z1 = 0.f;
                if (valid) {
                    z0 = acc[mt][nt][half * 2 + 0] + __ldg(&bias[col]);
                    z1 = acc[mt][nt][half * 2 + 1] + __ldg(&bias[col + 1]);
                    if (DO_GELU) { z0 = gelu_exact(z0); z1 = gelu_exact(z1); }
                }
                __nv_bfloat162 h2, l2;
                split_bf16(z0, h2.x, l2.x);
                split_bf16(z1, h2.y, l2.y);
                if (DO_GELU) {
                    *(__nv_bfloat162*)(g_hhi + base + col) = h2;
                    *(__nv_bfloat162*)(g_hlo + base + col) = l2;
                } else {
                    float2 o2 = make_float2(z0, z1);
                    *(float2*)(outY + base + col) = o2;
                    *(__nv_bfloat162*)(g_xhi + base + col) = h2;
                    *(__nv_bfloat162*)(g_xlo + base + col) = l2;
                }
            }
        }
    }
}

// ---------------------------------------------------------------------------
// split depth for latency-bound levels (capacity ~444 concurrent CTAs,
// gy = 12; path = waves * 72/ns). ns must divide 72.
static inline int pick_nspl(int M) {
    if (M >= 4096) return 0;
    if (M == 2048) return 3;     // 576 CTAs, path ~31
    if (M == 1024) return 4;     // 384 CTAs, path 18
    if (M == 512)  return 9;     // 432 CTAs, path 8
    if (M == 256)  return 18;    // 432 CTAs, path 4
    return 36;                   // M <= 128: 432 CTAs, path 2
}

extern "C" void kernel_launch(void* const* d_in, const int* in_sizes, int n_in,
                              void* d_out, int out_size) {
    const float* seq     = (const float*)d_in[0];
    const int*   lengths = (const int*)  d_in[1];
    const float* w1      = (const float*)d_in[2];
    const float* b1      = (const float*)d_in[3];
    const float* w2      = (const float*)d_in[4];
    const float* b2      = (const float*)d_in[5];
    float* out = (float*)d_out;

    cudaFuncSetAttribute(conv_mma<1, true, false>,
                         cudaFuncAttributeMaxDynamicSharedMemorySize, SMEM_BYTES);
    cudaFuncSetAttribute(conv_mma<2, false, false>,
                         cudaFuncAttributeMaxDynamicSharedMemorySize, SMEM_BYTES);
    cudaFuncSetAttribute(conv_mma<1, true, true>,
                         cudaFuncAttributeMaxDynamicSharedMemorySize, SMEM_BYTES);
    cudaFuncSetAttribute(conv_mma<2, false, true>,
                         cudaFuncAttributeMaxDynamicSharedMemorySize, SMEM_BYTES);

    prep_weights<<<256, 256>>>(w1, w2);
    prep_input<<<512, 256>>>(seq, lengths);
    mask_kernel<<<64, 256>>>(out, lengths);

    int P = 2048;
    long off = 0;
    for (int lvl = 0; lvl < NLEV; lvl++) {
        int Pout = (P - 1) / 2 + 1;
        // ---- conv1 ----
        int M1 = BZ * P;
        int gx1 = (M1 + BM - 1) / BM;
        int ns1 = pick_nspl(M1);
        if (ns1 == 0) {
            conv_mma<1, true, false><<<dim3(gx1, CDIM / BN), THREADS,
                                       SMEM_BYTES>>>(b1, nullptr, P, P,
                                                     lengths, lvl, 0);
        } else {
            conv_mma<1, true, true><<<dim3(gx1, CDIM / BN, ns1), THREADS,
                                      SMEM_BYTES>>>(b1, nullptr, P, P, lengths,
                                                    lvl, ns1);
            long pairs = (long)M1 * (CDIM / 2);
            int blocks = (int)((pairs + 255) / 256);
            if (blocks > 2048) blocks = 2048;
            reduce_split<true><<<blocks, 256>>>(b1, nullptr, P, lengths, lvl,
                                                M1, ns1);
        }
        // ---- conv2 ----
        int M2 = BZ * Pout;
        int gx2 = (M2 + BM - 1) / BM;
        int ns2 = pick_nspl(M2);
        if (ns2 == 0) {
            conv_mma<2, false, false><<<dim3(gx2, CDIM / BN), THREADS,
                                        SMEM_BYTES>>>(b2, out + off, P, Pout,
                                                      lengths, lvl, 0);
        } else {
            conv_mma<2, false, true><<<dim3(gx2, CDIM / BN, ns2), THREADS,
                                       SMEM_BYTES>>>(b2, nullptr, P, Pout,
                                                     lengths, lvl, ns2);
            long pairs = (long)M2 * (CDIM / 2);
            int blocks = (int)((pairs + 255) / 256);
            if (blocks > 2048) blocks = 2048;
            reduce_split<false><<<blocks, 256>>>(b2, out + off, Pout, lengths,
                                                 lvl, M2, ns2);
        }
        off += (long)BZ * Pout * CDIM + (long)BZ * Pout;
        P = Pout;
    }
}